// round 10
// baseline (speedup 1.0000x reference)
#include <cuda_runtime.h>
#include <cuda_fp16.h>
#include <cstdint>

#define BATCH 4
#define NNODE 20000
#define DN 64
#define DM 128
#define NE 160000
#define NL 2
#define ROWS (BATCH*NNODE)   // 80000
#define NEDGE_TOT (3*NE)     // 480000

// ---------------- scratch (device globals) ----------------------------------
__device__ float   g_H[(size_t)ROWS * DM];            // 41 MB
__device__ __half  g_G[(size_t)ROWS * 3 * DM];        // 61.5 MB (fp16)
__device__ float   g_Cterm[(size_t)NL * NNODE * DM];  // 20.5 MB
__device__ uint2   g_Wpre[(size_t)NL * 12288];        // fp16 B-fragment images
__device__ float   g_S0[(size_t)NNODE * 16];
__device__ float   g_S1[(size_t)NNODE * 16];
__device__ float   g_cnt[(size_t)NNODE * 4];
__device__ int     g_deg[NNODE];
__device__ int     g_off[NNODE + 1];
__device__ int     g_cursor[NNODE];
__device__ int2    g_entries[NEDGE_TOT];

__device__ __forceinline__ void cp16(void* dst, const void* src) {
    uint32_t d = (uint32_t)__cvta_generic_to_shared(dst);
    asm volatile("cp.async.cg.shared.global [%0], [%1], 16;" :: "r"(d), "l"(src));
}
__device__ __forceinline__ void cp_commit() {
    asm volatile("cp.async.commit_group;");
}
__device__ __forceinline__ void cp_wait0() {
    asm volatile("cp.async.wait_group 0;");
}

// ---------------- fp32 SGEMM (inproj only, K=64) -----------------------------
__global__ __launch_bounds__(256)
void sgemm128(const float* __restrict__ A, const float* __restrict__ W,
              const float* __restrict__ bias, float* __restrict__ C,
              int M, int K, int ldc, int coff)
{
    __shared__ float As[2][8][128];
    __shared__ float Bs[2][8][128];
    const int bm  = blockIdx.x * 128;
    const int tid = threadIdx.x;
    const int tx  = tid & 15;
    const int ty  = tid >> 4;

    float acc[8][8];
#pragma unroll
    for (int i = 0; i < 8; i++)
#pragma unroll
        for (int j = 0; j < 8; j++) acc[i][j] = 0.f;

    const int lm  = tid >> 1;
    const int lk4 = (tid & 1) * 4;
    const int lkB = tid >> 5;
    const int lnB = (tid & 31) * 4;
    const bool arow_ok = (bm + lm) < M;
    const float* Aptr = A + (size_t)(bm + lm) * K + lk4;

    float4 av = make_float4(0.f, 0.f, 0.f, 0.f);
    if (arow_ok) av = *reinterpret_cast<const float4*>(Aptr);
    float4 bv = *reinterpret_cast<const float4*>(W + (size_t)lkB * 128 + lnB);
    As[0][lk4 + 0][lm] = av.x; As[0][lk4 + 1][lm] = av.y;
    As[0][lk4 + 2][lm] = av.z; As[0][lk4 + 3][lm] = av.w;
    *reinterpret_cast<float4*>(&Bs[0][lkB][lnB]) = bv;
    __syncthreads();

    int cur = 0;
    for (int k0 = 8; k0 < K; k0 += 8) {
        av = make_float4(0.f, 0.f, 0.f, 0.f);
        if (arow_ok) av = *reinterpret_cast<const float4*>(Aptr + k0);
        bv = *reinterpret_cast<const float4*>(W + (size_t)(k0 + lkB) * 128 + lnB);
#pragma unroll
        for (int kk = 0; kk < 8; kk++) {
            float a[8], b[8];
#pragma unroll
            for (int i = 0; i < 8; i++) a[i] = As[cur][kk][ty * 8 + i];
#pragma unroll
            for (int j = 0; j < 8; j++) b[j] = Bs[cur][kk][tx * 8 + j];
#pragma unroll
            for (int i = 0; i < 8; i++)
#pragma unroll
                for (int j = 0; j < 8; j++)
                    acc[i][j] = fmaf(a[i], b[j], acc[i][j]);
        }
        int nxt = cur ^ 1;
        As[nxt][lk4 + 0][lm] = av.x; As[nxt][lk4 + 1][lm] = av.y;
        As[nxt][lk4 + 2][lm] = av.z; As[nxt][lk4 + 3][lm] = av.w;
        *reinterpret_cast<float4*>(&Bs[nxt][lkB][lnB]) = bv;
        __syncthreads();
        cur = nxt;
    }
#pragma unroll
    for (int kk = 0; kk < 8; kk++) {
        float a[8], b[8];
#pragma unroll
        for (int i = 0; i < 8; i++) a[i] = As[cur][kk][ty * 8 + i];
#pragma unroll
        for (int j = 0; j < 8; j++) b[j] = Bs[cur][kk][tx * 8 + j];
#pragma unroll
        for (int i = 0; i < 8; i++)
#pragma unroll
            for (int j = 0; j < 8; j++)
                acc[i][j] = fmaf(a[i], b[j], acc[i][j]);
    }
#pragma unroll
    for (int i = 0; i < 8; i++) {
        int gm = bm + ty * 8 + i;
        if (gm < M) {
#pragma unroll
            for (int j = 0; j < 8; j += 4) {
                int n = tx * 8 + j;
                float4 o;
                o.x = acc[i][j + 0] + bias[n + 0];
                o.y = acc[i][j + 1] + bias[n + 1];
                o.z = acc[i][j + 2] + bias[n + 2];
                o.w = acc[i][j + 3] + bias[n + 3];
                *reinterpret_cast<float4*>(C + (size_t)gm * ldc + coff + n) = o;
            }
        }
    }
}

// ---------------- W pre-conversion to fp16 B-fragment images -----------------
__global__ void prep_w_kernel(const float* __restrict__ node_W,
                              uint2* __restrict__ Wpre)
{
    int idx = blockIdx.x * blockDim.x + threadIdx.x;
    if (idx >= NL * 12288) return;
    int l  = idx / 12288;
    int r  = idx % 12288;
    int ch = r >> 9;
    int n  = (r >> 2) & 127;
    int lx = r & 3;
    int k0 = ch * 16 + 2 * lx;
    const float* W = node_W + (size_t)l * 3 * DM * DM;   // [384][128]
    __half2 lo = __floats2half2_rn(W[(size_t)k0 * 128 + n],       W[(size_t)(k0 + 1) * 128 + n]);
    __half2 hi = __floats2half2_rn(W[(size_t)(k0 + 8) * 128 + n], W[(size_t)(k0 + 9) * 128 + n]);
    uint2 v;
    v.x = *reinterpret_cast<uint32_t*>(&lo);
    v.y = *reinterpret_cast<uint32_t*>(&hi);
    Wpre[idx] = v;
}

// ---------------- fp16 tensor-core fused GEMM + Cterm + relu + H + LN -------
__global__ __launch_bounds__(256)
void gemm_ln_f16(const __half* __restrict__ G, const uint2* __restrict__ Wpre,
                 const float* __restrict__ H, const float* __restrict__ Ct,
                 const float* __restrict__ gamma, const float* __restrict__ beta,
                 float* __restrict__ out)
{
    __shared__ union SmemU {
        char  raw[2][10240];
        float C[64][132];
    } sm;

    const int tid  = threadIdx.x;
    const int bm   = blockIdx.x * 128;
    const int w    = tid >> 5;
    const int lane = tid & 31;
    const int ly   = lane >> 2;
    const int lx   = lane & 3;

    const int arow = tid >> 1;
    const int aseg = tid & 1;
    const char* Arow = reinterpret_cast<const char*>(G + (size_t)(bm + arow) * 384) + aseg * 16;
    const char* Wp   = reinterpret_cast<const char*>(Wpre);

    float acc[16][4];
#pragma unroll
    for (int nt = 0; nt < 16; nt++)
#pragma unroll
        for (int j = 0; j < 4; j++) acc[nt][j] = 0.f;

    auto stage = [&](int s, int ch) {
        cp16(sm.raw[s] + arow * 48 + aseg * 16, Arow + ch * 32);
        cp16(sm.raw[s] + 6144 + tid * 16,       Wp + (size_t)ch * 4096 + tid * 16);
    };

    stage(0, 0);
    cp_commit();

    int buf = 0;
#pragma unroll 1
    for (int ch = 0; ch < 24; ch++) {
        cp_wait0();
        __syncthreads();
        if (ch + 1 < 24) { stage(buf ^ 1, ch + 1); cp_commit(); }

        const char* A = sm.raw[buf];
        const char* B = sm.raw[buf] + 6144;
        uint32_t a0 = *reinterpret_cast<const uint32_t*>(A + (w * 16 + ly) * 48 + lx * 4);
        uint32_t a1 = *reinterpret_cast<const uint32_t*>(A + (w * 16 + ly + 8) * 48 + lx * 4);
        uint32_t a2 = *reinterpret_cast<const uint32_t*>(A + (w * 16 + ly) * 48 + 16 + lx * 4);
        uint32_t a3 = *reinterpret_cast<const uint32_t*>(A + (w * 16 + ly + 8) * 48 + 16 + lx * 4);
#pragma unroll
        for (int nt = 0; nt < 16; nt++) {
            uint2 b = *reinterpret_cast<const uint2*>(B + (nt * 8 + ly) * 32 + lx * 8);
            asm volatile(
                "mma.sync.aligned.m16n8k16.row.col.f32.f16.f16.f32 "
                "{%0,%1,%2,%3}, {%4,%5,%6,%7}, {%8,%9}, {%0,%1,%2,%3};"
                : "+f"(acc[nt][0]), "+f"(acc[nt][1]),
                  "+f"(acc[nt][2]), "+f"(acc[nt][3])
                : "r"(a0), "r"(a1), "r"(a2), "r"(a3), "r"(b.x), "r"(b.y));
        }
        buf ^= 1;
    }
    __syncthreads();

    const int nc = lane * 4;
    const float4 gg  = *reinterpret_cast<const float4*>(gamma + nc);
    const float4 bbv = *reinterpret_cast<const float4*>(beta + nc);

#pragma unroll 1
    for (int p = 0; p < 2; p++) {
        if ((w >> 2) == p) {
            const int lbase = (w & 3) * 16;
#pragma unroll
            for (int nt = 0; nt < 16; nt++) {
                *reinterpret_cast<float2*>(&sm.C[lbase + ly][nt * 8 + 2 * lx]) =
                    make_float2(acc[nt][0], acc[nt][1]);
                *reinterpret_cast<float2*>(&sm.C[lbase + ly + 8][nt * 8 + 2 * lx]) =
                    make_float2(acc[nt][2], acc[nt][3]);
            }
        }
        __syncthreads();
#pragma unroll 1
        for (int rr = 0; rr < 8; rr++) {
            const int lr   = w * 8 + rr;
            const int gm   = bm + p * 64 + lr;
            const int node = gm % NNODE;
            float4 cv  = *reinterpret_cast<const float4*>(&sm.C[lr][nc]);
            float4 ctv = *reinterpret_cast<const float4*>(Ct + (size_t)node * 128 + nc);
            float4 hv  = *reinterpret_cast<const float4*>(H + (size_t)gm * 128 + nc);
            float x0 = hv.x + fmaxf(cv.x + ctv.x, 0.f);
            float x1 = hv.y + fmaxf(cv.y + ctv.y, 0.f);
            float x2 = hv.z + fmaxf(cv.z + ctv.z, 0.f);
            float x3 = hv.w + fmaxf(cv.w + ctv.w, 0.f);

            float s = x0 + x1 + x2 + x3;
#pragma unroll
            for (int o = 16; o > 0; o >>= 1) s += __shfl_xor_sync(0xffffffffu, s, o);
            float mu = s * (1.f / 128.f);

            float d0 = x0 - mu, d1 = x1 - mu, d2 = x2 - mu, d3 = x3 - mu;
            float q = d0 * d0 + d1 * d1 + d2 * d2 + d3 * d3;
#pragma unroll
            for (int o = 16; o > 0; o >>= 1) q += __shfl_xor_sync(0xffffffffu, q, o);
            float rstd = rsqrtf(q * (1.f / 128.f) + 1e-5f);

            float4 ov;
            ov.x = d0 * rstd * gg.x + bbv.x;
            ov.y = d1 * rstd * gg.y + bbv.y;
            ov.z = d2 * rstd * gg.z + bbv.z;
            ov.w = d3 * rstd * gg.w + bbv.w;
            *reinterpret_cast<float4*>(out + (size_t)gm * 128 + nc) = ov;
        }
        __syncthreads();
    }
}

// ---------------- CSR build --------------------------------------------------
__global__ void zero_deg_kernel(int* __restrict__ deg)
{
    int i = blockIdx.x * blockDim.x + threadIdx.x;
    if (i < NNODE) deg[i] = 0;
}

__global__ void hist_kernel(const int* __restrict__ ei0,
                            const int* __restrict__ ei1,
                            const int* __restrict__ ei2,
                            int* __restrict__ deg)
{
    int i = blockIdx.x * blockDim.x + threadIdx.x;
    if (i >= NEDGE_TOT) return;
    int r = i / NE, e = i - r * NE;
    const int* ei = (r == 0) ? ei0 : (r == 1) ? ei1 : ei2;
    atomicAdd(deg + ei[NE + e], 1);
}

__global__ __launch_bounds__(256)
void scan_kernel(const int* __restrict__ deg, int* __restrict__ off,
                 int* __restrict__ cursor)
{
    __shared__ int warp_sums[8];
    __shared__ int s_carry;
    const int tid  = threadIdx.x;
    const int lane = tid & 31;
    const int wid  = tid >> 5;
    if (tid == 0) s_carry = 0;
    __syncthreads();

    for (int base = 0; base < NNODE; base += 256) {
        int i = base + tid;
        int x = (i < NNODE) ? deg[i] : 0;
        int v = x;
#pragma unroll
        for (int d = 1; d < 32; d <<= 1) {
            int t = __shfl_up_sync(0xffffffffu, v, d);
            if (lane >= d) v += t;
        }
        if (lane == 31) warp_sums[wid] = v;
        __syncthreads();
        if (wid == 0 && lane < 8) {
            int s = warp_sums[lane];
#pragma unroll
            for (int d = 1; d < 8; d <<= 1) {
                int t = __shfl_up_sync(0x000000ffu, s, d);
                if (lane >= d) s += t;
            }
            warp_sums[lane] = s;
        }
        __syncthreads();
        int add  = (wid > 0) ? warp_sums[wid - 1] : 0;
        int incl = v + add + s_carry;
        if (i < NNODE) { off[i] = incl - x; cursor[i] = incl - x; }
        __syncthreads();
        if (tid == 255) s_carry = incl;
        __syncthreads();
    }
    if (tid == 0) off[NNODE] = s_carry;
}

__global__ void fill_kernel(const int* __restrict__ ei0,
                            const int* __restrict__ ei1,
                            const int* __restrict__ ei2,
                            int* __restrict__ cursor,
                            int2* __restrict__ entries)
{
    int i = blockIdx.x * blockDim.x + threadIdx.x;
    if (i >= NEDGE_TOT) return;
    int r = i / NE, e = i - r * NE;
    const int* ei = (r == 0) ? ei0 : (r == 1) ? ei1 : ei2;
    int src = ei[e];
    int dst = ei[NE + e];
    int pos = atomicAdd(cursor + dst, 1);
    entries[pos] = make_int2(src, (r << 20) | e);
}

// ---------------- per-node stats: counts + edge-attr sums -------------------
__global__ __launch_bounds__(256)
void stats_kernel(const int* __restrict__ off, const int2* __restrict__ entries,
                  const float* __restrict__ ea0, const float* __restrict__ ea1,
                  float* __restrict__ S0, float* __restrict__ S1,
                  float* __restrict__ cnt)
{
    int warp = (blockIdx.x * blockDim.x + threadIdx.x) >> 5;
    int lane = threadIdx.x & 31;
    if (warp >= NNODE) return;
    const int jb = off[warp], je = off[warp + 1];
    float s0 = 0.f, s1 = 0.f;
    int c0 = 0, c1 = 0, c2 = 0;
    for (int j = jb; j < je; j++) {
        int2 m = entries[j];
        int rel = m.y >> 20, e = m.y & 0xFFFFF;
        if (rel == 0)      { c0++; if (lane < 16) s0 += ea0[(size_t)e * 16 + lane]; }
        else if (rel == 1) { c1++; if (lane < 16) s1 += ea1[(size_t)e * 16 + lane]; }
        else               { c2++; }
    }
    if (lane < 16) {
        S0[(size_t)warp * 16 + lane] = s0;
        S1[(size_t)warp * 16 + lane] = s1;
    }
    if (lane == 0) {
        cnt[(size_t)warp * 4 + 0] = (float)c0;
        cnt[(size_t)warp * 4 + 1] = (float)c1;
        cnt[(size_t)warp * 4 + 2] = (float)c2;
    }
}

// ---------------- Cterm: per-node, per-layer constant term ------------------
#define CT_NODES 16
__global__ __launch_bounds__(128)
void cterm_kernel(const float* __restrict__ S0, const float* __restrict__ S1,
                  const float* __restrict__ cnt,
                  const float* __restrict__ node_b, const float* __restrict__ edge_W,
                  const float* __restrict__ edge_b, float* __restrict__ Ct)
{
    const int l   = blockIdx.y;
    const int j   = threadIdx.x;
    __shared__ float eW0[16 * 128];
    __shared__ float eW1[16 * 128];
    __shared__ float nb0[128], nb1[128], nb2[128], eb0[128], eb1[128];
    __shared__ float sS[2][32];

    for (int k = 0; k < 16; k++) {
        eW0[k * 128 + j] = edge_W[((size_t)(l * 2 + 0) * 16 + k) * 128 + j];
        eW1[k * 128 + j] = edge_W[((size_t)(l * 2 + 1) * 16 + k) * 128 + j];
    }
    nb0[j] = node_b[(size_t)(l * 3 + 0) * 128 + j];
    nb1[j] = node_b[(size_t)(l * 3 + 1) * 128 + j];
    nb2[j] = node_b[(size_t)(l * 3 + 2) * 128 + j];
    eb0[j] = edge_b[(size_t)(l * 2 + 0) * 128 + j];
    eb1[j] = edge_b[(size_t)(l * 2 + 1) * 128 + j];
    __syncthreads();

    const int nbase = blockIdx.x * CT_NODES;
    for (int t = 0; t < CT_NODES; t++) {
        int node = nbase + t;
        int buf = t & 1;
        if (j < 16)      sS[buf][j] = S0[(size_t)node * 16 + j];
        else if (j < 32) sS[buf][j] = S1[(size_t)node * 16 + (j - 16)];
        __syncthreads();
        float c0 = cnt[(size_t)node * 4 + 0];
        float c1 = cnt[(size_t)node * 4 + 1];
        float c2 = cnt[(size_t)node * 4 + 2];
        float v = c0 * (nb0[j] + eb0[j]) + c1 * (nb1[j] + eb1[j]) + c2 * nb2[j];
#pragma unroll
        for (int k = 0; k < 16; k++) v = fmaf(sS[buf][k], eW0[k * 128 + j], v);
#pragma unroll
        for (int k = 0; k < 16; k++) v = fmaf(sS[buf][k + 16], eW1[k * 128 + j], v);
        Ct[((size_t)l * NNODE + node) * 128 + j] = v;
        __syncthreads();
    }
}

// ---------------- gather: 2-edge unrolled, fp16 G out ------------------------
__global__ __launch_bounds__(256)
void gather_kernel(const float* __restrict__ H, const int* __restrict__ off,
                   const int2* __restrict__ entries, __half* __restrict__ G)
{
    int warp = (blockIdx.x * blockDim.x + threadIdx.x) >> 5;
    int lane = threadIdx.x & 31;
    if (warp >= NNODE) return;
    const int node = warp;
    const int jb = off[node], je = off[node + 1];

    float4 a0[BATCH], a1[BATCH], a2[BATCH];
#pragma unroll
    for (int b = 0; b < BATCH; b++) {
        a0[b] = make_float4(0.f, 0.f, 0.f, 0.f);
        a1[b] = make_float4(0.f, 0.f, 0.f, 0.f);
        a2[b] = make_float4(0.f, 0.f, 0.f, 0.f);
    }

    int j = jb;
    for (; j + 2 <= je; j += 2) {
        // load both entries, then issue all 8 row loads before any use
        int2 mA = entries[j];
        int2 mB = entries[j + 1];
        const float* hA = H + (size_t)mA.x * 128 + lane * 4;
        const float* hB = H + (size_t)mB.x * 128 + lane * 4;
        float4 vA[BATCH], vB[BATCH];
#pragma unroll
        for (int b = 0; b < BATCH; b++)
            vA[b] = *reinterpret_cast<const float4*>(hA + (size_t)b * NNODE * 128);
#pragma unroll
        for (int b = 0; b < BATCH; b++)
            vB[b] = *reinterpret_cast<const float4*>(hB + (size_t)b * NNODE * 128);

        int relA = mA.y >> 20;
        if (relA == 0) {
#pragma unroll
            for (int b = 0; b < BATCH; b++) {
                a0[b].x += vA[b].x; a0[b].y += vA[b].y; a0[b].z += vA[b].z; a0[b].w += vA[b].w;
            }
        } else if (relA == 1) {
#pragma unroll
            for (int b = 0; b < BATCH; b++) {
                a1[b].x += vA[b].x; a1[b].y += vA[b].y; a1[b].z += vA[b].z; a1[b].w += vA[b].w;
            }
        } else {
#pragma unroll
            for (int b = 0; b < BATCH; b++) {
                a2[b].x += vA[b].x; a2[b].y += vA[b].y; a2[b].z += vA[b].z; a2[b].w += vA[b].w;
            }
        }
        int relB = mB.y >> 20;
        if (relB == 0) {
#pragma unroll
            for (int b = 0; b < BATCH; b++) {
                a0[b].x += vB[b].x; a0[b].y += vB[b].y; a0[b].z += vB[b].z; a0[b].w += vB[b].w;
            }
        } else if (relB == 1) {
#pragma unroll
            for (int b = 0; b < BATCH; b++) {
                a1[b].x += vB[b].x; a1[b].y += vB[b].y; a1[b].z += vB[b].z; a1[b].w += vB[b].w;
            }
        } else {
#pragma unroll
            for (int b = 0; b < BATCH; b++) {
                a2[b].x += vB[b].x; a2[b].y += vB[b].y; a2[b].z += vB[b].z; a2[b].w += vB[b].w;
            }
        }
    }
    if (j < je) {
        int2 m = entries[j];
        const float* hb = H + (size_t)m.x * 128 + lane * 4;
        float4 h[BATCH];
#pragma unroll
        for (int b = 0; b < BATCH; b++)
            h[b] = *reinterpret_cast<const float4*>(hb + (size_t)b * NNODE * 128);
        int rel = m.y >> 20;
        if (rel == 0) {
#pragma unroll
            for (int b = 0; b < BATCH; b++) {
                a0[b].x += h[b].x; a0[b].y += h[b].y; a0[b].z += h[b].z; a0[b].w += h[b].w;
            }
        } else if (rel == 1) {
#pragma unroll
            for (int b = 0; b < BATCH; b++) {
                a1[b].x += h[b].x; a1[b].y += h[b].y; a1[b].z += h[b].z; a1[b].w += h[b].w;
            }
        } else {
#pragma unroll
            for (int b = 0; b < BATCH; b++) {
                a2[b].x += h[b].x; a2[b].y += h[b].y; a2[b].z += h[b].z; a2[b].w += h[b].w;
            }
        }
    }

#pragma unroll
    for (int b = 0; b < BATCH; b++) {
        __half* gb = G + (size_t)(b * NNODE + node) * 384 + lane * 4;
        __half2 p0, p1;
        uint2 v;
        p0 = __floats2half2_rn(a0[b].x, a0[b].y);
        p1 = __floats2half2_rn(a0[b].z, a0[b].w);
        v.x = *reinterpret_cast<uint32_t*>(&p0);
        v.y = *reinterpret_cast<uint32_t*>(&p1);
        *reinterpret_cast<uint2*>(gb) = v;
        p0 = __floats2half2_rn(a1[b].x, a1[b].y);
        p1 = __floats2half2_rn(a1[b].z, a1[b].w);
        v.x = *reinterpret_cast<uint32_t*>(&p0);
        v.y = *reinterpret_cast<uint32_t*>(&p1);
        *reinterpret_cast<uint2*>(gb + 128) = v;
        p0 = __floats2half2_rn(a2[b].x, a2[b].y);
        p1 = __floats2half2_rn(a2[b].z, a2[b].w);
        v.x = *reinterpret_cast<uint32_t*>(&p0);
        v.y = *reinterpret_cast<uint32_t*>(&p1);
        *reinterpret_cast<uint2*>(gb + 256) = v;
    }
}

// ---------------- launch -----------------------------------------------------
extern "C" void kernel_launch(void* const* d_in, const int* in_sizes, int n_in,
                              void* d_out, int out_size)
{
    const float* node_feat = (const float*)d_in[0];
    const float* in_W      = (const float*)d_in[1];
    const float* in_b      = (const float*)d_in[2];
    const float* node_W    = (const float*)d_in[3];
    const float* node_b    = (const float*)d_in[4];
    const float* edge_W    = (const float*)d_in[5];
    const float* edge_b    = (const float*)d_in[6];
    const float* ln_g      = (const float*)d_in[7];
    const float* ln_b      = (const float*)d_in[8];
    const float* ea0       = (const float*)d_in[9];
    const float* ea1       = (const float*)d_in[10];
    const int*   ei0       = (const int*)d_in[11];
    const int*   ei1       = (const int*)d_in[12];
    const int*   ei2       = (const int*)d_in[13];
    float* out = (float*)d_out;

    float *H, *Ct, *S0, *S1, *cnt;
    __half* G;
    uint2* Wpre;
    int *deg, *off, *cursor;
    int2* entries;
    cudaGetSymbolAddress((void**)&H,       g_H);
    cudaGetSymbolAddress((void**)&G,       g_G);
    cudaGetSymbolAddress((void**)&Ct,      g_Cterm);
    cudaGetSymbolAddress((void**)&Wpre,    g_Wpre);
    cudaGetSymbolAddress((void**)&S0,      g_S0);
    cudaGetSymbolAddress((void**)&S1,      g_S1);
    cudaGetSymbolAddress((void**)&cnt,     g_cnt);
    cudaGetSymbolAddress((void**)&deg,     g_deg);
    cudaGetSymbolAddress((void**)&off,     g_off);
    cudaGetSymbolAddress((void**)&cursor,  g_cursor);
    cudaGetSymbolAddress((void**)&entries, g_entries);

    // CSR + per-node stats + per-layer constant terms + W pre-conversion
    zero_deg_kernel<<<(NNODE + 255) / 256, 256>>>(deg);
    hist_kernel<<<(NEDGE_TOT + 255) / 256, 256>>>(ei0, ei1, ei2, deg);
    scan_kernel<<<1, 256>>>(deg, off, cursor);
    fill_kernel<<<(NEDGE_TOT + 255) / 256, 256>>>(ei0, ei1, ei2, cursor, entries);
    stats_kernel<<<(NNODE * 32 + 255) / 256, 256>>>(off, entries, ea0, ea1, S0, S1, cnt);
    {
        dim3 grid(NNODE / CT_NODES, NL);
        cterm_kernel<<<grid, 128>>>(S0, S1, cnt, node_b, edge_W, edge_b, Ct);
    }
    prep_w_kernel<<<(NL * 12288 + 255) / 256, 256>>>(node_W, Wpre);

    // input projection (fp32 for accurate base H)
    sgemm128<<<(ROWS + 127) / 128, 256>>>(node_feat, in_W, in_b, H, ROWS, DN, DM, 0);

    for (int l = 0; l < NL; l++) {
        gather_kernel<<<(NNODE * 32 + 255) / 256, 256>>>(H, off, entries, G);
        float* dst = (l == NL - 1) ? out : H;
        gemm_ln_f16<<<ROWS / 128, 256>>>(
            G, Wpre + (size_t)l * 12288, H, Ct + (size_t)l * NNODE * DM,
            ln_g + (size_t)l * DM, ln_b + (size_t)l * DM, dst);
    }
}

// round 12
// speedup vs baseline: 1.0349x; 1.0349x over previous
#include <cuda_runtime.h>
#include <cuda_fp16.h>
#include <cstdint>

#define BATCH 4
#define NNODE 20000
#define DN 64
#define DM 128
#define NE 160000
#define NL 2
#define ROWS (BATCH*NNODE)   // 80000
#define NEDGE_TOT (3*NE)     // 480000

// ---------------- scratch (device globals) ----------------------------------
__device__ float   g_H[(size_t)ROWS * DM];            // 41 MB
__device__ __half  g_G[(size_t)ROWS * 3 * DM];        // 61.5 MB (fp16)
__device__ float   g_Cterm[(size_t)NL * NNODE * DM];  // 20.5 MB
__device__ uint2   g_Wpre[(size_t)NL * 12288];        // fp16 B-fragment images
__device__ float   g_S0[(size_t)NNODE * 16];
__device__ float   g_S1[(size_t)NNODE * 16];
__device__ float   g_cnt[(size_t)NNODE * 4];
__device__ int     g_deg[NNODE];
__device__ int     g_off[NNODE + 1];
__device__ int     g_cursor[NNODE];
__device__ int2    g_entries[NEDGE_TOT];

__device__ __forceinline__ void cp16(void* dst, const void* src) {
    uint32_t d = (uint32_t)__cvta_generic_to_shared(dst);
    asm volatile("cp.async.cg.shared.global [%0], [%1], 16;" :: "r"(d), "l"(src));
}
__device__ __forceinline__ void cp_commit() {
    asm volatile("cp.async.commit_group;");
}
__device__ __forceinline__ void cp_wait0() {
    asm volatile("cp.async.wait_group 0;");
}

// ---------------- fp32 SGEMM (inproj only, K=64) -----------------------------
__global__ __launch_bounds__(256)
void sgemm128(const float* __restrict__ A, const float* __restrict__ W,
              const float* __restrict__ bias, float* __restrict__ C,
              int M, int K, int ldc, int coff)
{
    __shared__ float As[2][8][128];
    __shared__ float Bs[2][8][128];
    const int bm  = blockIdx.x * 128;
    const int tid = threadIdx.x;
    const int tx  = tid & 15;
    const int ty  = tid >> 4;

    float acc[8][8];
#pragma unroll
    for (int i = 0; i < 8; i++)
#pragma unroll
        for (int j = 0; j < 8; j++) acc[i][j] = 0.f;

    const int lm  = tid >> 1;
    const int lk4 = (tid & 1) * 4;
    const int lkB = tid >> 5;
    const int lnB = (tid & 31) * 4;
    const bool arow_ok = (bm + lm) < M;
    const float* Aptr = A + (size_t)(bm + lm) * K + lk4;

    float4 av = make_float4(0.f, 0.f, 0.f, 0.f);
    if (arow_ok) av = *reinterpret_cast<const float4*>(Aptr);
    float4 bv = *reinterpret_cast<const float4*>(W + (size_t)lkB * 128 + lnB);
    As[0][lk4 + 0][lm] = av.x; As[0][lk4 + 1][lm] = av.y;
    As[0][lk4 + 2][lm] = av.z; As[0][lk4 + 3][lm] = av.w;
    *reinterpret_cast<float4*>(&Bs[0][lkB][lnB]) = bv;
    __syncthreads();

    int cur = 0;
    for (int k0 = 8; k0 < K; k0 += 8) {
        av = make_float4(0.f, 0.f, 0.f, 0.f);
        if (arow_ok) av = *reinterpret_cast<const float4*>(Aptr + k0);
        bv = *reinterpret_cast<const float4*>(W + (size_t)(k0 + lkB) * 128 + lnB);
#pragma unroll
        for (int kk = 0; kk < 8; kk++) {
            float a[8], b[8];
#pragma unroll
            for (int i = 0; i < 8; i++) a[i] = As[cur][kk][ty * 8 + i];
#pragma unroll
            for (int j = 0; j < 8; j++) b[j] = Bs[cur][kk][tx * 8 + j];
#pragma unroll
            for (int i = 0; i < 8; i++)
#pragma unroll
                for (int j = 0; j < 8; j++)
                    acc[i][j] = fmaf(a[i], b[j], acc[i][j]);
        }
        int nxt = cur ^ 1;
        As[nxt][lk4 + 0][lm] = av.x; As[nxt][lk4 + 1][lm] = av.y;
        As[nxt][lk4 + 2][lm] = av.z; As[nxt][lk4 + 3][lm] = av.w;
        *reinterpret_cast<float4*>(&Bs[nxt][lkB][lnB]) = bv;
        __syncthreads();
        cur = nxt;
    }
#pragma unroll
    for (int kk = 0; kk < 8; kk++) {
        float a[8], b[8];
#pragma unroll
        for (int i = 0; i < 8; i++) a[i] = As[cur][kk][ty * 8 + i];
#pragma unroll
        for (int j = 0; j < 8; j++) b[j] = Bs[cur][kk][tx * 8 + j];
#pragma unroll
        for (int i = 0; i < 8; i++)
#pragma unroll
            for (int j = 0; j < 8; j++)
                acc[i][j] = fmaf(a[i], b[j], acc[i][j]);
    }
#pragma unroll
    for (int i = 0; i < 8; i++) {
        int gm = bm + ty * 8 + i;
        if (gm < M) {
#pragma unroll
            for (int j = 0; j < 8; j += 4) {
                int n = tx * 8 + j;
                float4 o;
                o.x = acc[i][j + 0] + bias[n + 0];
                o.y = acc[i][j + 1] + bias[n + 1];
                o.z = acc[i][j + 2] + bias[n + 2];
                o.w = acc[i][j + 3] + bias[n + 3];
                *reinterpret_cast<float4*>(C + (size_t)gm * ldc + coff + n) = o;
            }
        }
    }
}

// ---------------- W pre-conversion to fp16 B-fragment images -----------------
__global__ void prep_w_kernel(const float* __restrict__ node_W,
                              uint2* __restrict__ Wpre)
{
    int idx = blockIdx.x * blockDim.x + threadIdx.x;
    if (idx >= NL * 12288) return;
    int l  = idx / 12288;
    int r  = idx % 12288;
    int ch = r >> 9;
    int n  = (r >> 2) & 127;
    int lx = r & 3;
    int k0 = ch * 16 + 2 * lx;
    const float* W = node_W + (size_t)l * 3 * DM * DM;   // [384][128]
    __half2 lo = __floats2half2_rn(W[(size_t)k0 * 128 + n],       W[(size_t)(k0 + 1) * 128 + n]);
    __half2 hi = __floats2half2_rn(W[(size_t)(k0 + 8) * 128 + n], W[(size_t)(k0 + 9) * 128 + n]);
    uint2 v;
    v.x = *reinterpret_cast<uint32_t*>(&lo);
    v.y = *reinterpret_cast<uint32_t*>(&hi);
    Wpre[idx] = v;
}

// ---------------- fp16 tensor-core fused GEMM + Cterm + relu + H + LN -------
__global__ __launch_bounds__(256)
void gemm_ln_f16(const __half* __restrict__ G, const uint2* __restrict__ Wpre,
                 const float* __restrict__ H, const float* __restrict__ Ct,
                 const float* __restrict__ gamma, const float* __restrict__ beta,
                 float* __restrict__ out)
{
    __shared__ union SmemU {
        char  raw[2][10240];
        float C[64][132];
    } sm;

    const int tid  = threadIdx.x;
    const int bm   = blockIdx.x * 128;
    const int w    = tid >> 5;
    const int lane = tid & 31;
    const int ly   = lane >> 2;
    const int lx   = lane & 3;

    const int arow = tid >> 1;
    const int aseg = tid & 1;
    const char* Arow = reinterpret_cast<const char*>(G + (size_t)(bm + arow) * 384) + aseg * 16;
    const char* Wp   = reinterpret_cast<const char*>(Wpre);

    float acc[16][4];
#pragma unroll
    for (int nt = 0; nt < 16; nt++)
#pragma unroll
        for (int j = 0; j < 4; j++) acc[nt][j] = 0.f;

    auto stage = [&](int s, int ch) {
        cp16(sm.raw[s] + arow * 48 + aseg * 16, Arow + ch * 32);
        cp16(sm.raw[s] + 6144 + tid * 16,       Wp + (size_t)ch * 4096 + tid * 16);
    };

    stage(0, 0);
    cp_commit();

    int buf = 0;
#pragma unroll 1
    for (int ch = 0; ch < 24; ch++) {
        cp_wait0();
        __syncthreads();
        if (ch + 1 < 24) { stage(buf ^ 1, ch + 1); cp_commit(); }

        const char* A = sm.raw[buf];
        const char* B = sm.raw[buf] + 6144;
        uint32_t a0 = *reinterpret_cast<const uint32_t*>(A + (w * 16 + ly) * 48 + lx * 4);
        uint32_t a1 = *reinterpret_cast<const uint32_t*>(A + (w * 16 + ly + 8) * 48 + lx * 4);
        uint32_t a2 = *reinterpret_cast<const uint32_t*>(A + (w * 16 + ly) * 48 + 16 + lx * 4);
        uint32_t a3 = *reinterpret_cast<const uint32_t*>(A + (w * 16 + ly + 8) * 48 + 16 + lx * 4);
#pragma unroll
        for (int nt = 0; nt < 16; nt++) {
            uint2 b = *reinterpret_cast<const uint2*>(B + (nt * 8 + ly) * 32 + lx * 8);
            asm volatile(
                "mma.sync.aligned.m16n8k16.row.col.f32.f16.f16.f32 "
                "{%0,%1,%2,%3}, {%4,%5,%6,%7}, {%8,%9}, {%0,%1,%2,%3};"
                : "+f"(acc[nt][0]), "+f"(acc[nt][1]),
                  "+f"(acc[nt][2]), "+f"(acc[nt][3])
                : "r"(a0), "r"(a1), "r"(a2), "r"(a3), "r"(b.x), "r"(b.y));
        }
        buf ^= 1;
    }
    __syncthreads();

    const int nc = lane * 4;
    const float4 gg  = *reinterpret_cast<const float4*>(gamma + nc);
    const float4 bbv = *reinterpret_cast<const float4*>(beta + nc);

#pragma unroll 1
    for (int p = 0; p < 2; p++) {
        if ((w >> 2) == p) {
            const int lbase = (w & 3) * 16;
#pragma unroll
            for (int nt = 0; nt < 16; nt++) {
                *reinterpret_cast<float2*>(&sm.C[lbase + ly][nt * 8 + 2 * lx]) =
                    make_float2(acc[nt][0], acc[nt][1]);
                *reinterpret_cast<float2*>(&sm.C[lbase + ly + 8][nt * 8 + 2 * lx]) =
                    make_float2(acc[nt][2], acc[nt][3]);
            }
        }
        __syncthreads();
#pragma unroll 1
        for (int rr = 0; rr < 8; rr++) {
            const int lr   = w * 8 + rr;
            const int gm   = bm + p * 64 + lr;
            const int node = gm % NNODE;
            float4 cv  = *reinterpret_cast<const float4*>(&sm.C[lr][nc]);
            float4 ctv = *reinterpret_cast<const float4*>(Ct + (size_t)node * 128 + nc);
            float4 hv  = *reinterpret_cast<const float4*>(H + (size_t)gm * 128 + nc);
            float x0 = hv.x + fmaxf(cv.x + ctv.x, 0.f);
            float x1 = hv.y + fmaxf(cv.y + ctv.y, 0.f);
            float x2 = hv.z + fmaxf(cv.z + ctv.z, 0.f);
            float x3 = hv.w + fmaxf(cv.w + ctv.w, 0.f);

            float s = x0 + x1 + x2 + x3;
#pragma unroll
            for (int o = 16; o > 0; o >>= 1) s += __shfl_xor_sync(0xffffffffu, s, o);
            float mu = s * (1.f / 128.f);

            float d0 = x0 - mu, d1 = x1 - mu, d2 = x2 - mu, d3 = x3 - mu;
            float q = d0 * d0 + d1 * d1 + d2 * d2 + d3 * d3;
#pragma unroll
            for (int o = 16; o > 0; o >>= 1) q += __shfl_xor_sync(0xffffffffu, q, o);
            float rstd = rsqrtf(q * (1.f / 128.f) + 1e-5f);

            float4 ov;
            ov.x = d0 * rstd * gg.x + bbv.x;
            ov.y = d1 * rstd * gg.y + bbv.y;
            ov.z = d2 * rstd * gg.z + bbv.z;
            ov.w = d3 * rstd * gg.w + bbv.w;
            *reinterpret_cast<float4*>(out + (size_t)gm * 128 + nc) = ov;
        }
        __syncthreads();
    }
}

// ---------------- CSR build --------------------------------------------------
__global__ void zero_deg_kernel(int* __restrict__ deg)
{
    int i = blockIdx.x * blockDim.x + threadIdx.x;
    if (i < NNODE) deg[i] = 0;
}

__global__ void hist_kernel(const int* __restrict__ ei0,
                            const int* __restrict__ ei1,
                            const int* __restrict__ ei2,
                            int* __restrict__ deg)
{
    int i = blockIdx.x * blockDim.x + threadIdx.x;
    if (i >= NEDGE_TOT) return;
    int r = i / NE, e = i - r * NE;
    const int* ei = (r == 0) ? ei0 : (r == 1) ? ei1 : ei2;
    atomicAdd(deg + ei[NE + e], 1);
}

__global__ __launch_bounds__(256)
void scan_kernel(const int* __restrict__ deg, int* __restrict__ off,
                 int* __restrict__ cursor)
{
    __shared__ int warp_sums[8];
    __shared__ int s_carry;
    const int tid  = threadIdx.x;
    const int lane = tid & 31;
    const int wid  = tid >> 5;
    if (tid == 0) s_carry = 0;
    __syncthreads();

    for (int base = 0; base < NNODE; base += 256) {
        int i = base + tid;
        int x = (i < NNODE) ? deg[i] : 0;
        int v = x;
#pragma unroll
        for (int d = 1; d < 32; d <<= 1) {
            int t = __shfl_up_sync(0xffffffffu, v, d);
            if (lane >= d) v += t;
        }
        if (lane == 31) warp_sums[wid] = v;
        __syncthreads();
        if (wid == 0 && lane < 8) {
            int s = warp_sums[lane];
#pragma unroll
            for (int d = 1; d < 8; d <<= 1) {
                int t = __shfl_up_sync(0x000000ffu, s, d);
                if (lane >= d) s += t;
            }
            warp_sums[lane] = s;
        }
        __syncthreads();
        int add  = (wid > 0) ? warp_sums[wid - 1] : 0;
        int incl = v + add + s_carry;
        if (i < NNODE) { off[i] = incl - x; cursor[i] = incl - x; }
        __syncthreads();
        if (tid == 255) s_carry = incl;
        __syncthreads();
    }
    if (tid == 0) off[NNODE] = s_carry;
}

__global__ void fill_kernel(const int* __restrict__ ei0,
                            const int* __restrict__ ei1,
                            const int* __restrict__ ei2,
                            int* __restrict__ cursor,
                            int2* __restrict__ entries)
{
    int i = blockIdx.x * blockDim.x + threadIdx.x;
    if (i >= NEDGE_TOT) return;
    int r = i / NE, e = i - r * NE;
    const int* ei = (r == 0) ? ei0 : (r == 1) ? ei1 : ei2;
    int src = ei[e];
    int dst = ei[NE + e];
    int pos = atomicAdd(cursor + dst, 1);
    entries[pos] = make_int2(src, (r << 20) | e);
}

// ---------------- per-node stats: counts + edge-attr sums -------------------
__global__ __launch_bounds__(256)
void stats_kernel(const int* __restrict__ off, const int2* __restrict__ entries,
                  const float* __restrict__ ea0, const float* __restrict__ ea1,
                  float* __restrict__ S0, float* __restrict__ S1,
                  float* __restrict__ cnt)
{
    int warp = (blockIdx.x * blockDim.x + threadIdx.x) >> 5;
    int lane = threadIdx.x & 31;
    if (warp >= NNODE) return;
    const int jb = off[warp], je = off[warp + 1];
    float s0 = 0.f, s1 = 0.f;
    int c0 = 0, c1 = 0, c2 = 0;
    for (int j = jb; j < je; j++) {
        int2 m = entries[j];
        int rel = m.y >> 20, e = m.y & 0xFFFFF;
        if (rel == 0)      { c0++; if (lane < 16) s0 += ea0[(size_t)e * 16 + lane]; }
        else if (rel == 1) { c1++; if (lane < 16) s1 += ea1[(size_t)e * 16 + lane]; }
        else               { c2++; }
    }
    if (lane < 16) {
        S0[(size_t)warp * 16 + lane] = s0;
        S1[(size_t)warp * 16 + lane] = s1;
    }
    if (lane == 0) {
        cnt[(size_t)warp * 4 + 0] = (float)c0;
        cnt[(size_t)warp * 4 + 1] = (float)c1;
        cnt[(size_t)warp * 4 + 2] = (float)c2;
    }
}

// ---------------- Cterm: per-node, per-layer constant term ------------------
#define CT_NODES 16
__global__ __launch_bounds__(128)
void cterm_kernel(const float* __restrict__ S0, const float* __restrict__ S1,
                  const float* __restrict__ cnt,
                  const float* __restrict__ node_b, const float* __restrict__ edge_W,
                  const float* __restrict__ edge_b, float* __restrict__ Ct)
{
    const int l   = blockIdx.y;
    const int j   = threadIdx.x;
    __shared__ float eW0[16 * 128];
    __shared__ float eW1[16 * 128];
    __shared__ float nb0[128], nb1[128], nb2[128], eb0[128], eb1[128];
    __shared__ float sS[2][32];

    for (int k = 0; k < 16; k++) {
        eW0[k * 128 + j] = edge_W[((size_t)(l * 2 + 0) * 16 + k) * 128 + j];
        eW1[k * 128 + j] = edge_W[((size_t)(l * 2 + 1) * 16 + k) * 128 + j];
    }
    nb0[j] = node_b[(size_t)(l * 3 + 0) * 128 + j];
    nb1[j] = node_b[(size_t)(l * 3 + 1) * 128 + j];
    nb2[j] = node_b[(size_t)(l * 3 + 2) * 128 + j];
    eb0[j] = edge_b[(size_t)(l * 2 + 0) * 128 + j];
    eb1[j] = edge_b[(size_t)(l * 2 + 1) * 128 + j];
    __syncthreads();

    const int nbase = blockIdx.x * CT_NODES;
    for (int t = 0; t < CT_NODES; t++) {
        int node = nbase + t;
        int buf = t & 1;
        if (j < 16)      sS[buf][j] = S0[(size_t)node * 16 + j];
        else if (j < 32) sS[buf][j] = S1[(size_t)node * 16 + (j - 16)];
        __syncthreads();
        float c0 = cnt[(size_t)node * 4 + 0];
        float c1 = cnt[(size_t)node * 4 + 1];
        float c2 = cnt[(size_t)node * 4 + 2];
        float v = c0 * (nb0[j] + eb0[j]) + c1 * (nb1[j] + eb1[j]) + c2 * nb2[j];
#pragma unroll
        for (int k = 0; k < 16; k++) v = fmaf(sS[buf][k], eW0[k * 128 + j], v);
#pragma unroll
        for (int k = 0; k < 16; k++) v = fmaf(sS[buf][k + 16], eW1[k * 128 + j], v);
        Ct[((size_t)l * NNODE + node) * 128 + j] = v;
        __syncthreads();
    }
}

// ---------------- gather: one warp per (node, batch-pair), fp16 G out -------
#define BPW 2   // batches per warp
__global__ __launch_bounds__(256)
void gather_kernel(const float* __restrict__ H, const int* __restrict__ off,
                   const int2* __restrict__ entries, __half* __restrict__ G)
{
    int gw   = (blockIdx.x * blockDim.x + threadIdx.x) >> 5;
    int lane = threadIdx.x & 31;
    if (gw >= NNODE * 2) return;
    const int node = gw >> 1;
    const int b0   = (gw & 1) * BPW;     // batches [b0, b0+BPW)
    const int jb = off[node], je = off[node + 1];

    float4 a0[BPW], a1[BPW], a2[BPW];
#pragma unroll
    for (int b = 0; b < BPW; b++) {
        a0[b] = make_float4(0.f, 0.f, 0.f, 0.f);
        a1[b] = make_float4(0.f, 0.f, 0.f, 0.f);
        a2[b] = make_float4(0.f, 0.f, 0.f, 0.f);
    }

    const float* Hb = H + (size_t)(b0 * NNODE) * 128 + lane * 4;
    for (int j = jb; j < je; j++) {
        int2 m = entries[j];
        int src = m.x;
        int rel = m.y >> 20;
        const float* hb = Hb + (size_t)src * 128;
        float4 h[BPW];
#pragma unroll
        for (int b = 0; b < BPW; b++)
            h[b] = *reinterpret_cast<const float4*>(hb + (size_t)b * NNODE * 128);
        if (rel == 0) {
#pragma unroll
            for (int b = 0; b < BPW; b++) {
                a0[b].x += h[b].x; a0[b].y += h[b].y; a0[b].z += h[b].z; a0[b].w += h[b].w;
            }
        } else if (rel == 1) {
#pragma unroll
            for (int b = 0; b < BPW; b++) {
                a1[b].x += h[b].x; a1[b].y += h[b].y; a1[b].z += h[b].z; a1[b].w += h[b].w;
            }
        } else {
#pragma unroll
            for (int b = 0; b < BPW; b++) {
                a2[b].x += h[b].x; a2[b].y += h[b].y; a2[b].z += h[b].z; a2[b].w += h[b].w;
            }
        }
    }

#pragma unroll
    for (int b = 0; b < BPW; b++) {
        __half* gb = G + (size_t)((b0 + b) * NNODE + node) * 384 + lane * 4;
        __half2 p0, p1;
        uint2 v;
        p0 = __floats2half2_rn(a0[b].x, a0[b].y);
        p1 = __floats2half2_rn(a0[b].z, a0[b].w);
        v.x = *reinterpret_cast<uint32_t*>(&p0);
        v.y = *reinterpret_cast<uint32_t*>(&p1);
        *reinterpret_cast<uint2*>(gb) = v;
        p0 = __floats2half2_rn(a1[b].x, a1[b].y);
        p1 = __floats2half2_rn(a1[b].z, a1[b].w);
        v.x = *reinterpret_cast<uint32_t*>(&p0);
        v.y = *reinterpret_cast<uint32_t*>(&p1);
        *reinterpret_cast<uint2*>(gb + 128) = v;
        p0 = __floats2half2_rn(a2[b].x, a2[b].y);
        p1 = __floats2half2_rn(a2[b].z, a2[b].w);
        v.x = *reinterpret_cast<uint32_t*>(&p0);
        v.y = *reinterpret_cast<uint32_t*>(&p1);
        *reinterpret_cast<uint2*>(gb + 256) = v;
    }
}

// ---------------- launch -----------------------------------------------------
extern "C" void kernel_launch(void* const* d_in, const int* in_sizes, int n_in,
                              void* d_out, int out_size)
{
    const float* node_feat = (const float*)d_in[0];
    const float* in_W      = (const float*)d_in[1];
    const float* in_b      = (const float*)d_in[2];
    const float* node_W    = (const float*)d_in[3];
    const float* node_b    = (const float*)d_in[4];
    const float* edge_W    = (const float*)d_in[5];
    const float* edge_b    = (const float*)d_in[6];
    const float* ln_g      = (const float*)d_in[7];
    const float* ln_b      = (const float*)d_in[8];
    const float* ea0       = (const float*)d_in[9];
    const float* ea1       = (const float*)d_in[10];
    const int*   ei0       = (const int*)d_in[11];
    const int*   ei1       = (const int*)d_in[12];
    const int*   ei2       = (const int*)d_in[13];
    float* out = (float*)d_out;

    float *H, *Ct, *S0, *S1, *cnt;
    __half* G;
    uint2* Wpre;
    int *deg, *off, *cursor;
    int2* entries;
    cudaGetSymbolAddress((void**)&H,       g_H);
    cudaGetSymbolAddress((void**)&G,       g_G);
    cudaGetSymbolAddress((void**)&Ct,      g_Cterm);
    cudaGetSymbolAddress((void**)&Wpre,    g_Wpre);
    cudaGetSymbolAddress((void**)&S0,      g_S0);
    cudaGetSymbolAddress((void**)&S1,      g_S1);
    cudaGetSymbolAddress((void**)&cnt,     g_cnt);
    cudaGetSymbolAddress((void**)&deg,     g_deg);
    cudaGetSymbolAddress((void**)&off,     g_off);
    cudaGetSymbolAddress((void**)&cursor,  g_cursor);
    cudaGetSymbolAddress((void**)&entries, g_entries);

    // CSR + per-node stats + per-layer constant terms + W pre-conversion
    zero_deg_kernel<<<(NNODE + 255) / 256, 256>>>(deg);
    hist_kernel<<<(NEDGE_TOT + 255) / 256, 256>>>(ei0, ei1, ei2, deg);
    scan_kernel<<<1, 256>>>(deg, off, cursor);
    fill_kernel<<<(NEDGE_TOT + 255) / 256, 256>>>(ei0, ei1, ei2, cursor, entries);
    stats_kernel<<<(NNODE * 32 + 255) / 256, 256>>>(off, entries, ea0, ea1, S0, S1, cnt);
    {
        dim3 grid(NNODE / CT_NODES, NL);
        cterm_kernel<<<grid, 128>>>(S0, S1, cnt, node_b, edge_W, edge_b, Ct);
    }
    prep_w_kernel<<<(NL * 12288 + 255) / 256, 256>>>(node_W, Wpre);

    // input projection (fp32 for accurate base H)
    sgemm128<<<(ROWS + 127) / 128, 256>>>(node_feat, in_W, in_b, H, ROWS, DN, DM, 0);

    for (int l = 0; l < NL; l++) {
        gather_kernel<<<(NNODE * 2 * 32 + 255) / 256, 256>>>(H, off, entries, G);
        float* dst = (l == NL - 1) ? out : H;
        gemm_ln_f16<<<ROWS / 128, 256>>>(
            G, Wpre + (size_t)l * 12288, H, Ct + (size_t)l * NNODE * DM,
            ln_g + (size_t)l * DM, ln_b + (size_t)l * DM, dst);
    }
}

// round 15
// speedup vs baseline: 1.1011x; 1.0640x over previous
#include <cuda_runtime.h>
#include <cuda_fp16.h>
#include <cstdint>

#define BATCH 4
#define NNODE 20000
#define DN 64
#define DM 128
#define NE 160000
#define NL 2
#define ROWS (BATCH*NNODE)   // 80000
#define NEDGE_TOT (3*NE)     // 480000

// ---------------- scratch (device globals) ----------------------------------
__device__ float   g_H[(size_t)ROWS * DM];            // 41 MB
__device__ __half  g_G[(size_t)ROWS * 3 * DM];        // 61.5 MB (fp16)
__device__ float   g_Cterm[(size_t)NL * NNODE * DM];  // 20.5 MB
__device__ uint2   g_Wpre[(size_t)NL * 12288];        // fp16 B-fragment images
__device__ float   g_S0[(size_t)NNODE * 16];
__device__ float   g_S1[(size_t)NNODE * 16];
__device__ int4    g_cnti[NNODE];                     // per-(node,rel) counts
__device__ int     g_off[NNODE + 1];
__device__ int     g_cursor3[NNODE * 3];
__device__ int     g_srcs[NEDGE_TOT];                 // rel-partitioned srcs

__device__ __forceinline__ void cp16(void* dst, const void* src) {
    uint32_t d = (uint32_t)__cvta_generic_to_shared(dst);
    asm volatile("cp.async.cg.shared.global [%0], [%1], 16;" :: "r"(d), "l"(src));
}
__device__ __forceinline__ void cp_commit() {
    asm volatile("cp.async.commit_group;");
}
__device__ __forceinline__ void cp_wait0() {
    asm volatile("cp.async.wait_group 0;");
}

// ---------------- fp32 SGEMM (inproj only, K=64) -----------------------------
__global__ __launch_bounds__(256)
void sgemm128(const float* __restrict__ A, const float* __restrict__ W,
              const float* __restrict__ bias, float* __restrict__ C,
              int M, int K, int ldc, int coff)
{
    __shared__ float As[2][8][128];
    __shared__ float Bs[2][8][128];
    const int bm  = blockIdx.x * 128;
    const int tid = threadIdx.x;
    const int tx  = tid & 15;
    const int ty  = tid >> 4;

    float acc[8][8];
#pragma unroll
    for (int i = 0; i < 8; i++)
#pragma unroll
        for (int j = 0; j < 8; j++) acc[i][j] = 0.f;

    const int lm  = tid >> 1;
    const int lk4 = (tid & 1) * 4;
    const int lkB = tid >> 5;
    const int lnB = (tid & 31) * 4;
    const bool arow_ok = (bm + lm) < M;
    const float* Aptr = A + (size_t)(bm + lm) * K + lk4;

    float4 av = make_float4(0.f, 0.f, 0.f, 0.f);
    if (arow_ok) av = *reinterpret_cast<const float4*>(Aptr);
    float4 bv = *reinterpret_cast<const float4*>(W + (size_t)lkB * 128 + lnB);
    As[0][lk4 + 0][lm] = av.x; As[0][lk4 + 1][lm] = av.y;
    As[0][lk4 + 2][lm] = av.z; As[0][lk4 + 3][lm] = av.w;
    *reinterpret_cast<float4*>(&Bs[0][lkB][lnB]) = bv;
    __syncthreads();

    int cur = 0;
    for (int k0 = 8; k0 < K; k0 += 8) {
        av = make_float4(0.f, 0.f, 0.f, 0.f);
        if (arow_ok) av = *reinterpret_cast<const float4*>(Aptr + k0);
        bv = *reinterpret_cast<const float4*>(W + (size_t)(k0 + lkB) * 128 + lnB);
#pragma unroll
        for (int kk = 0; kk < 8; kk++) {
            float a[8], b[8];
#pragma unroll
            for (int i = 0; i < 8; i++) a[i] = As[cur][kk][ty * 8 + i];
#pragma unroll
            for (int j = 0; j < 8; j++) b[j] = Bs[cur][kk][tx * 8 + j];
#pragma unroll
            for (int i = 0; i < 8; i++)
#pragma unroll
                for (int j = 0; j < 8; j++)
                    acc[i][j] = fmaf(a[i], b[j], acc[i][j]);
        }
        int nxt = cur ^ 1;
        As[nxt][lk4 + 0][lm] = av.x; As[nxt][lk4 + 1][lm] = av.y;
        As[nxt][lk4 + 2][lm] = av.z; As[nxt][lk4 + 3][lm] = av.w;
        *reinterpret_cast<float4*>(&Bs[nxt][lkB][lnB]) = bv;
        __syncthreads();
        cur = nxt;
    }
#pragma unroll
    for (int kk = 0; kk < 8; kk++) {
        float a[8], b[8];
#pragma unroll
        for (int i = 0; i < 8; i++) a[i] = As[cur][kk][ty * 8 + i];
#pragma unroll
        for (int j = 0; j < 8; j++) b[j] = Bs[cur][kk][tx * 8 + j];
#pragma unroll
        for (int i = 0; i < 8; i++)
#pragma unroll
            for (int j = 0; j < 8; j++)
                acc[i][j] = fmaf(a[i], b[j], acc[i][j]);
    }
#pragma unroll
    for (int i = 0; i < 8; i++) {
        int gm = bm + ty * 8 + i;
        if (gm < M) {
#pragma unroll
            for (int j = 0; j < 8; j += 4) {
                int n = tx * 8 + j;
                float4 o;
                o.x = acc[i][j + 0] + bias[n + 0];
                o.y = acc[i][j + 1] + bias[n + 1];
                o.z = acc[i][j + 2] + bias[n + 2];
                o.w = acc[i][j + 3] + bias[n + 3];
                *reinterpret_cast<float4*>(C + (size_t)gm * ldc + coff + n) = o;
            }
        }
    }
}

// ---------------- W pre-conversion to fp16 B-fragment images -----------------
__global__ void prep_w_kernel(const float* __restrict__ node_W,
                              uint2* __restrict__ Wpre)
{
    int idx = blockIdx.x * blockDim.x + threadIdx.x;
    if (idx >= NL * 12288) return;
    int l  = idx / 12288;
    int r  = idx % 12288;
    int ch = r >> 9;
    int n  = (r >> 2) & 127;
    int lx = r & 3;
    int k0 = ch * 16 + 2 * lx;
    const float* W = node_W + (size_t)l * 3 * DM * DM;   // [384][128]
    __half2 lo = __floats2half2_rn(W[(size_t)k0 * 128 + n],       W[(size_t)(k0 + 1) * 128 + n]);
    __half2 hi = __floats2half2_rn(W[(size_t)(k0 + 8) * 128 + n], W[(size_t)(k0 + 9) * 128 + n]);
    uint2 v;
    v.x = *reinterpret_cast<uint32_t*>(&lo);
    v.y = *reinterpret_cast<uint32_t*>(&hi);
    Wpre[idx] = v;
}

// ---------------- fp16 tensor-core fused GEMM + Cterm + relu + H + LN -------
__global__ __launch_bounds__(256)
void gemm_ln_f16(const __half* __restrict__ G, const uint2* __restrict__ Wpre,
                 const float* __restrict__ H, const float* __restrict__ Ct,
                 const float* __restrict__ gamma, const float* __restrict__ beta,
                 float* __restrict__ out)
{
    __shared__ union SmemU {
        char  raw[2][10240];
        float C[64][132];
    } sm;

    const int tid  = threadIdx.x;
    const int bm   = blockIdx.x * 128;
    const int w    = tid >> 5;
    const int lane = tid & 31;
    const int ly   = lane >> 2;
    const int lx   = lane & 3;

    const int arow = tid >> 1;
    const int aseg = tid & 1;
    const char* Arow = reinterpret_cast<const char*>(G + (size_t)(bm + arow) * 384) + aseg * 16;
    const char* Wp   = reinterpret_cast<const char*>(Wpre);

    float acc[16][4];
#pragma unroll
    for (int nt = 0; nt < 16; nt++)
#pragma unroll
        for (int j = 0; j < 4; j++) acc[nt][j] = 0.f;

    auto stage = [&](int s, int ch) {
        cp16(sm.raw[s] + arow * 48 + aseg * 16, Arow + ch * 32);
        cp16(sm.raw[s] + 6144 + tid * 16,       Wp + (size_t)ch * 4096 + tid * 16);
    };

    stage(0, 0);
    cp_commit();

    int buf = 0;
#pragma unroll 1
    for (int ch = 0; ch < 24; ch++) {
        cp_wait0();
        __syncthreads();
        if (ch + 1 < 24) { stage(buf ^ 1, ch + 1); cp_commit(); }

        const char* A = sm.raw[buf];
        const char* B = sm.raw[buf] + 6144;
        uint32_t a0 = *reinterpret_cast<const uint32_t*>(A + (w * 16 + ly) * 48 + lx * 4);
        uint32_t a1 = *reinterpret_cast<const uint32_t*>(A + (w * 16 + ly + 8) * 48 + lx * 4);
        uint32_t a2 = *reinterpret_cast<const uint32_t*>(A + (w * 16 + ly) * 48 + 16 + lx * 4);
        uint32_t a3 = *reinterpret_cast<const uint32_t*>(A + (w * 16 + ly + 8) * 48 + 16 + lx * 4);
#pragma unroll
        for (int nt = 0; nt < 16; nt++) {
            uint2 b = *reinterpret_cast<const uint2*>(B + (nt * 8 + ly) * 32 + lx * 8);
            asm volatile(
                "mma.sync.aligned.m16n8k16.row.col.f32.f16.f16.f32 "
                "{%0,%1,%2,%3}, {%4,%5,%6,%7}, {%8,%9}, {%0,%1,%2,%3};"
                : "+f"(acc[nt][0]), "+f"(acc[nt][1]),
                  "+f"(acc[nt][2]), "+f"(acc[nt][3])
                : "r"(a0), "r"(a1), "r"(a2), "r"(a3), "r"(b.x), "r"(b.y));
        }
        buf ^= 1;
    }
    __syncthreads();

    const int nc = lane * 4;
    const float4 gg  = *reinterpret_cast<const float4*>(gamma + nc);
    const float4 bbv = *reinterpret_cast<const float4*>(beta + nc);

#pragma unroll 1
    for (int p = 0; p < 2; p++) {
        if ((w >> 2) == p) {
            const int lbase = (w & 3) * 16;
#pragma unroll
            for (int nt = 0; nt < 16; nt++) {
                *reinterpret_cast<float2*>(&sm.C[lbase + ly][nt * 8 + 2 * lx]) =
                    make_float2(acc[nt][0], acc[nt][1]);
                *reinterpret_cast<float2*>(&sm.C[lbase + ly + 8][nt * 8 + 2 * lx]) =
                    make_float2(acc[nt][2], acc[nt][3]);
            }
        }
        __syncthreads();
#pragma unroll 1
        for (int rr = 0; rr < 8; rr++) {
            const int lr   = w * 8 + rr;
            const int gm   = bm + p * 64 + lr;
            const int node = gm % NNODE;
            float4 cv  = *reinterpret_cast<const float4*>(&sm.C[lr][nc]);
            float4 ctv = *reinterpret_cast<const float4*>(Ct + (size_t)node * 128 + nc);
            float4 hv  = *reinterpret_cast<const float4*>(H + (size_t)gm * 128 + nc);
            float x0 = hv.x + fmaxf(cv.x + ctv.x, 0.f);
            float x1 = hv.y + fmaxf(cv.y + ctv.y, 0.f);
            float x2 = hv.z + fmaxf(cv.z + ctv.z, 0.f);
            float x3 = hv.w + fmaxf(cv.w + ctv.w, 0.f);

            float s = x0 + x1 + x2 + x3;
#pragma unroll
            for (int o = 16; o > 0; o >>= 1) s += __shfl_xor_sync(0xffffffffu, s, o);
            float mu = s * (1.f / 128.f);

            float d0 = x0 - mu, d1 = x1 - mu, d2 = x2 - mu, d3 = x3 - mu;
            float q = d0 * d0 + d1 * d1 + d2 * d2 + d3 * d3;
#pragma unroll
            for (int o = 16; o > 0; o >>= 1) q += __shfl_xor_sync(0xffffffffu, q, o);
            float rstd = rsqrtf(q * (1.f / 128.f) + 1e-5f);

            float4 ov;
            ov.x = d0 * rstd * gg.x + bbv.x;
            ov.y = d1 * rstd * gg.y + bbv.y;
            ov.z = d2 * rstd * gg.z + bbv.z;
            ov.w = d3 * rstd * gg.w + bbv.w;
            *reinterpret_cast<float4*>(out + (size_t)gm * 128 + nc) = ov;
        }
        __syncthreads();
    }
}

// ---------------- build: per-(node,rel) counts, offsets, sorted srcs --------
__global__ void zero_build_kernel(int4* __restrict__ cnti,
                                  float* __restrict__ S0, float* __restrict__ S1)
{
    int i = blockIdx.x * blockDim.x + threadIdx.x;
    if (i < NNODE) cnti[i] = make_int4(0, 0, 0, 0);
    if (i < NNODE * 16) { S0[i] = 0.f; S1[i] = 0.f; }
}

__global__ void hist3_kernel(const int* __restrict__ ei0,
                             const int* __restrict__ ei1,
                             const int* __restrict__ ei2,
                             int4* __restrict__ cnti)
{
    int i = blockIdx.x * blockDim.x + threadIdx.x;
    if (i >= NEDGE_TOT) return;
    int r = i / NE, e = i - r * NE;
    const int* ei = (r == 0) ? ei0 : (r == 1) ? ei1 : ei2;
    int dst = ei[NE + e];
    atomicAdd(reinterpret_cast<int*>(cnti + dst) + r, 1);
}

// single-block exclusive scan over per-node totals -> off
__global__ __launch_bounds__(256)
void scan_kernel(const int4* __restrict__ cnti, int* __restrict__ off)
{
    __shared__ int warp_sums[8];
    __shared__ int s_carry;
    const int tid  = threadIdx.x;
    const int lane = tid & 31;
    const int wid  = tid >> 5;
    if (tid == 0) s_carry = 0;
    __syncthreads();

    for (int base = 0; base < NNODE; base += 256) {
        int i = base + tid;
        int x = 0;
        if (i < NNODE) {
            int4 c = cnti[i];
            x = c.x + c.y + c.z;
        }
        int v = x;
#pragma unroll
        for (int d = 1; d < 32; d <<= 1) {
            int t = __shfl_up_sync(0xffffffffu, v, d);
            if (lane >= d) v += t;
        }
        if (lane == 31) warp_sums[wid] = v;
        __syncthreads();
        if (wid == 0 && lane < 8) {
            int s = warp_sums[lane];
#pragma unroll
            for (int d = 1; d < 8; d <<= 1) {
                int t = __shfl_up_sync(0x000000ffu, s, d);
                if (lane >= d) s += t;
            }
            warp_sums[lane] = s;
        }
        __syncthreads();
        int add  = (wid > 0) ? warp_sums[wid - 1] : 0;
        int incl = v + add + s_carry;
        if (i < NNODE) off[i] = incl - x;
        __syncthreads();
        if (tid == 255) s_carry = incl;
        __syncthreads();
    }
    if (tid == 0) off[NNODE] = s_carry;
}

__global__ void cursor3_kernel(const int4* __restrict__ cnti,
                               const int* __restrict__ off,
                               int* __restrict__ cursor3)
{
    int i = blockIdx.x * blockDim.x + threadIdx.x;
    if (i >= NNODE) return;
    int4 c = cnti[i];
    int base = off[i];
    cursor3[i * 3 + 0] = base;
    cursor3[i * 3 + 1] = base + c.x;
    cursor3[i * 3 + 2] = base + c.x + c.y;
}

__global__ void fill3_kernel(const int* __restrict__ ei0,
                             const int* __restrict__ ei1,
                             const int* __restrict__ ei2,
                             int* __restrict__ cursor3,
                             int* __restrict__ srcs)
{
    int i = blockIdx.x * blockDim.x + threadIdx.x;
    if (i >= NEDGE_TOT) return;
    int r = i / NE, e = i - r * NE;
    const int* ei = (r == 0) ? ei0 : (r == 1) ? ei1 : ei2;
    int src = ei[e];
    int dst = ei[NE + e];
    int pos = atomicAdd(cursor3 + dst * 3 + r, 1);
    srcs[pos] = src;
}

// ---------------- edge-attr scatter: S_r[dst] += ea_r[e] --------------------
__global__ void ea_scatter_kernel(const float* __restrict__ ea0,
                                  const float* __restrict__ ea1,
                                  const int* __restrict__ ei0,
                                  const int* __restrict__ ei1,
                                  float* __restrict__ S0, float* __restrict__ S1)
{
    int i = blockIdx.x * blockDim.x + threadIdx.x;
    if (i >= 2 * NE * 16) return;
    int rel = i / (NE * 16);
    int rem = i - rel * (NE * 16);
    int e = rem >> 4;
    int l = rem & 15;
    if (rel == 0) {
        int dst = ei0[NE + e];
        atomicAdd(S0 + (size_t)dst * 16 + l, ea0[(size_t)e * 16 + l]);
    } else {
        int dst = ei1[NE + e];
        atomicAdd(S1 + (size_t)dst * 16 + l, ea1[(size_t)e * 16 + l]);
    }
}

// ---------------- Cterm: per-node, per-layer constant term ------------------
#define CT_NODES 16
__global__ __launch_bounds__(128)
void cterm_kernel(const float* __restrict__ S0, const float* __restrict__ S1,
                  const int4* __restrict__ cnti,
                  const float* __restrict__ node_b, const float* __restrict__ edge_W,
                  const float* __restrict__ edge_b, float* __restrict__ Ct)
{
    const int l   = blockIdx.y;
    const int j   = threadIdx.x;
    __shared__ float eW0[16 * 128];
    __shared__ float eW1[16 * 128];
    __shared__ float nb0[128], nb1[128], nb2[128], eb0[128], eb1[128];
    __shared__ float sS[2][32];

    for (int k = 0; k < 16; k++) {
        eW0[k * 128 + j] = edge_W[((size_t)(l * 2 + 0) * 16 + k) * 128 + j];
        eW1[k * 128 + j] = edge_W[((size_t)(l * 2 + 1) * 16 + k) * 128 + j];
    }
    nb0[j] = node_b[(size_t)(l * 3 + 0) * 128 + j];
    nb1[j] = node_b[(size_t)(l * 3 + 1) * 128 + j];
    nb2[j] = node_b[(size_t)(l * 3 + 2) * 128 + j];
    eb0[j] = edge_b[(size_t)(l * 2 + 0) * 128 + j];
    eb1[j] = edge_b[(size_t)(l * 2 + 1) * 128 + j];
    __syncthreads();

    const int nbase = blockIdx.x * CT_NODES;
    for (int t = 0; t < CT_NODES; t++) {
        int node = nbase + t;
        int buf = t & 1;
        if (j < 16)      sS[buf][j] = S0[(size_t)node * 16 + j];
        else if (j < 32) sS[buf][j] = S1[(size_t)node * 16 + (j - 16)];
        __syncthreads();
        int4 ci = cnti[node];
        float c0 = (float)ci.x;
        float c1 = (float)ci.y;
        float c2 = (float)ci.z;
        float v = c0 * (nb0[j] + eb0[j]) + c1 * (nb1[j] + eb1[j]) + c2 * nb2[j];
#pragma unroll
        for (int k = 0; k < 16; k++) v = fmaf(sS[buf][k], eW0[k * 128 + j], v);
#pragma unroll
        for (int k = 0; k < 16; k++) v = fmaf(sS[buf][k + 16], eW1[k * 128 + j], v);
        Ct[((size_t)l * NNODE + node) * 128 + j] = v;
        __syncthreads();
    }
}

// ---------------- gather: branchless rel-partitioned, warp per (node,bpair) -
#define BPW 2   // batches per warp
__global__ __launch_bounds__(256)
void gather_kernel(const float* __restrict__ H, const int* __restrict__ off,
                   const int4* __restrict__ cnti, const int* __restrict__ srcs,
                   __half* __restrict__ G)
{
    int gw   = (blockIdx.x * blockDim.x + threadIdx.x) >> 5;
    int lane = threadIdx.x & 31;
    if (gw >= NNODE * 2) return;
    const int node = gw >> 1;
    const int b0   = (gw & 1) * BPW;
    const int jb = off[node];
    const int4 c = cnti[node];
    const int j0e = jb + c.x;
    const int j1e = j0e + c.y;
    const int je  = j1e + c.z;

    float4 a0[BPW], a1[BPW], a2[BPW];
#pragma unroll
    for (int b = 0; b < BPW; b++) {
        a0[b] = make_float4(0.f, 0.f, 0.f, 0.f);
        a1[b] = make_float4(0.f, 0.f, 0.f, 0.f);
        a2[b] = make_float4(0.f, 0.f, 0.f, 0.f);
    }

    const float* Hb = H + (size_t)(b0 * NNODE) * 128 + lane * 4;

    for (int j = jb; j < j0e; j++) {
        int src = srcs[j];
        const float* hb = Hb + (size_t)src * 128;
#pragma unroll
        for (int b = 0; b < BPW; b++) {
            float4 h = *reinterpret_cast<const float4*>(hb + (size_t)b * NNODE * 128);
            a0[b].x += h.x; a0[b].y += h.y; a0[b].z += h.z; a0[b].w += h.w;
        }
    }
    for (int j = j0e; j < j1e; j++) {
        int src = srcs[j];
        const float* hb = Hb + (size_t)src * 128;
#pragma unroll
        for (int b = 0; b < BPW; b++) {
            float4 h = *reinterpret_cast<const float4*>(hb + (size_t)b * NNODE * 128);
            a1[b].x += h.x; a1[b].y += h.y; a1[b].z += h.z; a1[b].w += h.w;
        }
    }
    for (int j = j1e; j < je; j++) {
        int src = srcs[j];
        const float* hb = Hb + (size_t)src * 128;
#pragma unroll
        for (int b = 0; b < BPW; b++) {
            float4 h = *reinterpret_cast<const float4*>(hb + (size_t)b * NNODE * 128);
            a2[b].x += h.x; a2[b].y += h.y; a2[b].z += h.z; a2[b].w += h.w;
        }
    }

#pragma unroll
    for (int b = 0; b < BPW; b++) {
        __half* gb = G + (size_t)((b0 + b) * NNODE + node) * 384 + lane * 4;
        __half2 p0, p1;
        uint2 v;
        p0 = __floats2half2_rn(a0[b].x, a0[b].y);
        p1 = __floats2half2_rn(a0[b].z, a0[b].w);
        v.x = *reinterpret_cast<uint32_t*>(&p0);
        v.y = *reinterpret_cast<uint32_t*>(&p1);
        *reinterpret_cast<uint2*>(gb) = v;
        p0 = __floats2half2_rn(a1[b].x, a1[b].y);
        p1 = __floats2half2_rn(a1[b].z, a1[b].w);
        v.x = *reinterpret_cast<uint32_t*>(&p0);
        v.y = *reinterpret_cast<uint32_t*>(&p1);
        *reinterpret_cast<uint2*>(gb + 128) = v;
        p0 = __floats2half2_rn(a2[b].x, a2[b].y);
        p1 = __floats2half2_rn(a2[b].z, a2[b].w);
        v.x = *reinterpret_cast<uint32_t*>(&p0);
        v.y = *reinterpret_cast<uint32_t*>(&p1);
        *reinterpret_cast<uint2*>(gb + 256) = v;
    }
}

// ---------------- launch -----------------------------------------------------
extern "C" void kernel_launch(void* const* d_in, const int* in_sizes, int n_in,
                              void* d_out, int out_size)
{
    const float* node_feat = (const float*)d_in[0];
    const float* in_W      = (const float*)d_in[1];
    const float* in_b      = (const float*)d_in[2];
    const float* node_W    = (const float*)d_in[3];
    const float* node_b    = (const float*)d_in[4];
    const float* edge_W    = (const float*)d_in[5];
    const float* edge_b    = (const float*)d_in[6];
    const float* ln_g      = (const float*)d_in[7];
    const float* ln_b      = (const float*)d_in[8];
    const float* ea0       = (const float*)d_in[9];
    const float* ea1       = (const float*)d_in[10];
    const int*   ei0       = (const int*)d_in[11];
    const int*   ei1       = (const int*)d_in[12];
    const int*   ei2       = (const int*)d_in[13];
    float* out = (float*)d_out;

    float *H, *Ct, *S0, *S1;
    __half* G;
    uint2* Wpre;
    int4* cnti;
    int *off, *cursor3, *srcs;
    cudaGetSymbolAddress((void**)&H,       g_H);
    cudaGetSymbolAddress((void**)&G,       g_G);
    cudaGetSymbolAddress((void**)&Ct,      g_Cterm);
    cudaGetSymbolAddress((void**)&Wpre,    g_Wpre);
    cudaGetSymbolAddress((void**)&S0,      g_S0);
    cudaGetSymbolAddress((void**)&S1,      g_S1);
    cudaGetSymbolAddress((void**)&cnti,    g_cnti);
    cudaGetSymbolAddress((void**)&off,     g_off);
    cudaGetSymbolAddress((void**)&cursor3, g_cursor3);
    cudaGetSymbolAddress((void**)&srcs,    g_srcs);

    // build: counts, offsets, rel-partitioned srcs, edge-attr sums
    zero_build_kernel<<<(NNODE * 16 + 255) / 256, 256>>>(cnti, S0, S1);
    hist3_kernel<<<(NEDGE_TOT + 255) / 256, 256>>>(ei0, ei1, ei2, cnti);
    scan_kernel<<<1, 256>>>(cnti, off);
    cursor3_kernel<<<(NNODE + 255) / 256, 256>>>(cnti, off, cursor3);
    fill3_kernel<<<(NEDGE_TOT + 255) / 256, 256>>>(ei0, ei1, ei2, cursor3, srcs);
    ea_scatter_kernel<<<(2 * NE * 16 + 255) / 256, 256>>>(ea0, ea1, ei0, ei1, S0, S1);
    {
        dim3 grid(NNODE / CT_NODES, NL);
        cterm_kernel<<<grid, 128>>>(S0, S1, cnti, node_b, edge_W, edge_b, Ct);
    }
    prep_w_kernel<<<(NL * 12288 + 255) / 256, 256>>>(node_W, Wpre);

    // input projection (fp32 for accurate base H)
    sgemm128<<<(ROWS + 127) / 128, 256>>>(node_feat, in_W, in_b, H, ROWS, DN, DM, 0);

    for (int l = 0; l < NL; l++) {
        gather_kernel<<<(NNODE * 2 * 32 + 255) / 256, 256>>>(H, off, cnti, srcs, G);
        float* dst = (l == NL - 1) ? out : H;
        gemm_ln_f16<<<ROWS / 128, 256>>>(
            G, Wpre + (size_t)l * 12288, H, Ct + (size_t)l * NNODE * DM,
            ln_g + (size_t)l * DM, ln_b + (size_t)l * DM, dst);
    }
}

// round 16
// speedup vs baseline: 1.1517x; 1.0459x over previous
#include <cuda_runtime.h>
#include <cuda_fp16.h>
#include <cstdint>

#define BATCH 4
#define NNODE 20000
#define DN 64
#define DM 128
#define NE 160000
#define NL 2
#define ROWS (BATCH*NNODE)   // 80000
#define NEDGE_TOT (3*NE)     // 480000

// ---------------- scratch (device globals) ----------------------------------
__device__ float   g_H[(size_t)ROWS * DM];            // 41 MB
__device__ __half2 g_Hh[(size_t)ROWS * 64];           // 20.5 MB fp16 mirror
__device__ __half  g_G[(size_t)ROWS * 3 * DM];        // 61.5 MB (fp16)
__device__ float   g_Cterm[(size_t)NL * NNODE * DM];  // 20.5 MB
__device__ uint2   g_Wpre[(size_t)NL * 12288];        // fp16 B-fragment images
__device__ float   g_S0[(size_t)NNODE * 16];
__device__ float   g_S1[(size_t)NNODE * 16];
__device__ int4    g_cnti[NNODE];                     // per-(node,rel) counts
__device__ int     g_off[NNODE + 1];
__device__ int     g_cursor3[NNODE * 3];
__device__ int     g_srcs[NEDGE_TOT];                 // rel-partitioned srcs

__device__ __forceinline__ void cp16(void* dst, const void* src) {
    uint32_t d = (uint32_t)__cvta_generic_to_shared(dst);
    asm volatile("cp.async.cg.shared.global [%0], [%1], 16;" :: "r"(d), "l"(src));
}
__device__ __forceinline__ void cp_commit() {
    asm volatile("cp.async.commit_group;");
}
__device__ __forceinline__ void cp_wait0() {
    asm volatile("cp.async.wait_group 0;");
}

// ---------------- fp32 SGEMM (inproj; emits fp16 mirror too) -----------------
__global__ __launch_bounds__(256)
void sgemm128(const float* __restrict__ A, const float* __restrict__ W,
              const float* __restrict__ bias, float* __restrict__ C,
              __half2* __restrict__ Ch,
              int M, int K, int ldc, int coff)
{
    __shared__ float As[2][8][128];
    __shared__ float Bs[2][8][128];
    const int bm  = blockIdx.x * 128;
    const int tid = threadIdx.x;
    const int tx  = tid & 15;
    const int ty  = tid >> 4;

    float acc[8][8];
#pragma unroll
    for (int i = 0; i < 8; i++)
#pragma unroll
        for (int j = 0; j < 8; j++) acc[i][j] = 0.f;

    const int lm  = tid >> 1;
    const int lk4 = (tid & 1) * 4;
    const int lkB = tid >> 5;
    const int lnB = (tid & 31) * 4;
    const bool arow_ok = (bm + lm) < M;
    const float* Aptr = A + (size_t)(bm + lm) * K + lk4;

    float4 av = make_float4(0.f, 0.f, 0.f, 0.f);
    if (arow_ok) av = *reinterpret_cast<const float4*>(Aptr);
    float4 bv = *reinterpret_cast<const float4*>(W + (size_t)lkB * 128 + lnB);
    As[0][lk4 + 0][lm] = av.x; As[0][lk4 + 1][lm] = av.y;
    As[0][lk4 + 2][lm] = av.z; As[0][lk4 + 3][lm] = av.w;
    *reinterpret_cast<float4*>(&Bs[0][lkB][lnB]) = bv;
    __syncthreads();

    int cur = 0;
    for (int k0 = 8; k0 < K; k0 += 8) {
        av = make_float4(0.f, 0.f, 0.f, 0.f);
        if (arow_ok) av = *reinterpret_cast<const float4*>(Aptr + k0);
        bv = *reinterpret_cast<const float4*>(W + (size_t)(k0 + lkB) * 128 + lnB);
#pragma unroll
        for (int kk = 0; kk < 8; kk++) {
            float a[8], b[8];
#pragma unroll
            for (int i = 0; i < 8; i++) a[i] = As[cur][kk][ty * 8 + i];
#pragma unroll
            for (int j = 0; j < 8; j++) b[j] = Bs[cur][kk][tx * 8 + j];
#pragma unroll
            for (int i = 0; i < 8; i++)
#pragma unroll
                for (int j = 0; j < 8; j++)
                    acc[i][j] = fmaf(a[i], b[j], acc[i][j]);
        }
        int nxt = cur ^ 1;
        As[nxt][lk4 + 0][lm] = av.x; As[nxt][lk4 + 1][lm] = av.y;
        As[nxt][lk4 + 2][lm] = av.z; As[nxt][lk4 + 3][lm] = av.w;
        *reinterpret_cast<float4*>(&Bs[nxt][lkB][lnB]) = bv;
        __syncthreads();
        cur = nxt;
    }
#pragma unroll
    for (int kk = 0; kk < 8; kk++) {
        float a[8], b[8];
#pragma unroll
        for (int i = 0; i < 8; i++) a[i] = As[cur][kk][ty * 8 + i];
#pragma unroll
        for (int j = 0; j < 8; j++) b[j] = Bs[cur][kk][tx * 8 + j];
#pragma unroll
        for (int i = 0; i < 8; i++)
#pragma unroll
            for (int j = 0; j < 8; j++)
                acc[i][j] = fmaf(a[i], b[j], acc[i][j]);
    }
#pragma unroll
    for (int i = 0; i < 8; i++) {
        int gm = bm + ty * 8 + i;
        if (gm < M) {
#pragma unroll
            for (int j = 0; j < 8; j += 4) {
                int n = tx * 8 + j;
                float4 o;
                o.x = acc[i][j + 0] + bias[n + 0];
                o.y = acc[i][j + 1] + bias[n + 1];
                o.z = acc[i][j + 2] + bias[n + 2];
                o.w = acc[i][j + 3] + bias[n + 3];
                *reinterpret_cast<float4*>(C + (size_t)gm * ldc + coff + n) = o;
                __half2 h0 = __floats2half2_rn(o.x, o.y);
                __half2 h1 = __floats2half2_rn(o.z, o.w);
                *reinterpret_cast<uint2*>(Ch + (size_t)gm * 64 + n / 2) =
                    make_uint2(*reinterpret_cast<uint32_t*>(&h0),
                               *reinterpret_cast<uint32_t*>(&h1));
            }
        }
    }
}

// ---------------- W pre-conversion to fp16 B-fragment images -----------------
__global__ void prep_w_kernel(const float* __restrict__ node_W,
                              uint2* __restrict__ Wpre)
{
    int idx = blockIdx.x * blockDim.x + threadIdx.x;
    if (idx >= NL * 12288) return;
    int l  = idx / 12288;
    int r  = idx % 12288;
    int ch = r >> 9;
    int n  = (r >> 2) & 127;
    int lx = r & 3;
    int k0 = ch * 16 + 2 * lx;
    const float* W = node_W + (size_t)l * 3 * DM * DM;   // [384][128]
    __half2 lo = __floats2half2_rn(W[(size_t)k0 * 128 + n],       W[(size_t)(k0 + 1) * 128 + n]);
    __half2 hi = __floats2half2_rn(W[(size_t)(k0 + 8) * 128 + n], W[(size_t)(k0 + 9) * 128 + n]);
    uint2 v;
    v.x = *reinterpret_cast<uint32_t*>(&lo);
    v.y = *reinterpret_cast<uint32_t*>(&hi);
    Wpre[idx] = v;
}

// ---------------- fp16 tensor-core fused GEMM + Cterm + relu + H + LN -------
__global__ __launch_bounds__(256)
void gemm_ln_f16(const __half* __restrict__ G, const uint2* __restrict__ Wpre,
                 const float* __restrict__ H, const float* __restrict__ Ct,
                 const float* __restrict__ gamma, const float* __restrict__ beta,
                 float* __restrict__ out, __half2* __restrict__ outh)
{
    __shared__ union SmemU {
        char  raw[2][10240];
        float C[64][132];
    } sm;

    const int tid  = threadIdx.x;
    const int bm   = blockIdx.x * 128;
    const int w    = tid >> 5;
    const int lane = tid & 31;
    const int ly   = lane >> 2;
    const int lx   = lane & 3;

    const int arow = tid >> 1;
    const int aseg = tid & 1;
    const char* Arow = reinterpret_cast<const char*>(G + (size_t)(bm + arow) * 384) + aseg * 16;
    const char* Wp   = reinterpret_cast<const char*>(Wpre);

    float acc[16][4];
#pragma unroll
    for (int nt = 0; nt < 16; nt++)
#pragma unroll
        for (int j = 0; j < 4; j++) acc[nt][j] = 0.f;

    auto stage = [&](int s, int ch) {
        cp16(sm.raw[s] + arow * 48 + aseg * 16, Arow + ch * 32);
        cp16(sm.raw[s] + 6144 + tid * 16,       Wp + (size_t)ch * 4096 + tid * 16);
    };

    stage(0, 0);
    cp_commit();

    int buf = 0;
#pragma unroll 1
    for (int ch = 0; ch < 24; ch++) {
        cp_wait0();
        __syncthreads();
        if (ch + 1 < 24) { stage(buf ^ 1, ch + 1); cp_commit(); }

        const char* A = sm.raw[buf];
        const char* B = sm.raw[buf] + 6144;
        uint32_t a0 = *reinterpret_cast<const uint32_t*>(A + (w * 16 + ly) * 48 + lx * 4);
        uint32_t a1 = *reinterpret_cast<const uint32_t*>(A + (w * 16 + ly + 8) * 48 + lx * 4);
        uint32_t a2 = *reinterpret_cast<const uint32_t*>(A + (w * 16 + ly) * 48 + 16 + lx * 4);
        uint32_t a3 = *reinterpret_cast<const uint32_t*>(A + (w * 16 + ly + 8) * 48 + 16 + lx * 4);
#pragma unroll
        for (int nt = 0; nt < 16; nt++) {
            uint2 b = *reinterpret_cast<const uint2*>(B + (nt * 8 + ly) * 32 + lx * 8);
            asm volatile(
                "mma.sync.aligned.m16n8k16.row.col.f32.f16.f16.f32 "
                "{%0,%1,%2,%3}, {%4,%5,%6,%7}, {%8,%9}, {%0,%1,%2,%3};"
                : "+f"(acc[nt][0]), "+f"(acc[nt][1]),
                  "+f"(acc[nt][2]), "+f"(acc[nt][3])
                : "r"(a0), "r"(a1), "r"(a2), "r"(a3), "r"(b.x), "r"(b.y));
        }
        buf ^= 1;
    }
    __syncthreads();

    const int nc = lane * 4;
    const float4 gg  = *reinterpret_cast<const float4*>(gamma + nc);
    const float4 bbv = *reinterpret_cast<const float4*>(beta + nc);

#pragma unroll 1
    for (int p = 0; p < 2; p++) {
        if ((w >> 2) == p) {
            const int lbase = (w & 3) * 16;
#pragma unroll
            for (int nt = 0; nt < 16; nt++) {
                *reinterpret_cast<float2*>(&sm.C[lbase + ly][nt * 8 + 2 * lx]) =
                    make_float2(acc[nt][0], acc[nt][1]);
                *reinterpret_cast<float2*>(&sm.C[lbase + ly + 8][nt * 8 + 2 * lx]) =
                    make_float2(acc[nt][2], acc[nt][3]);
            }
        }
        __syncthreads();
#pragma unroll 1
        for (int rr = 0; rr < 8; rr++) {
            const int lr   = w * 8 + rr;
            const int gm   = bm + p * 64 + lr;
            const int node = gm % NNODE;
            float4 cv  = *reinterpret_cast<const float4*>(&sm.C[lr][nc]);
            float4 ctv = *reinterpret_cast<const float4*>(Ct + (size_t)node * 128 + nc);
            float4 hv  = *reinterpret_cast<const float4*>(H + (size_t)gm * 128 + nc);
            float x0 = hv.x + fmaxf(cv.x + ctv.x, 0.f);
            float x1 = hv.y + fmaxf(cv.y + ctv.y, 0.f);
            float x2 = hv.z + fmaxf(cv.z + ctv.z, 0.f);
            float x3 = hv.w + fmaxf(cv.w + ctv.w, 0.f);

            float s = x0 + x1 + x2 + x3;
#pragma unroll
            for (int o = 16; o > 0; o >>= 1) s += __shfl_xor_sync(0xffffffffu, s, o);
            float mu = s * (1.f / 128.f);

            float d0 = x0 - mu, d1 = x1 - mu, d2 = x2 - mu, d3 = x3 - mu;
            float q = d0 * d0 + d1 * d1 + d2 * d2 + d3 * d3;
#pragma unroll
            for (int o = 16; o > 0; o >>= 1) q += __shfl_xor_sync(0xffffffffu, q, o);
            float rstd = rsqrtf(q * (1.f / 128.f) + 1e-5f);

            float4 ov;
            ov.x = d0 * rstd * gg.x + bbv.x;
            ov.y = d1 * rstd * gg.y + bbv.y;
            ov.z = d2 * rstd * gg.z + bbv.z;
            ov.w = d3 * rstd * gg.w + bbv.w;
            *reinterpret_cast<float4*>(out + (size_t)gm * 128 + nc) = ov;
            if (outh) {
                __half2 h0 = __floats2half2_rn(ov.x, ov.y);
                __half2 h1 = __floats2half2_rn(ov.z, ov.w);
                *reinterpret_cast<uint2*>(outh + (size_t)gm * 64 + lane * 2) =
                    make_uint2(*reinterpret_cast<uint32_t*>(&h0),
                               *reinterpret_cast<uint32_t*>(&h1));
            }
        }
        __syncthreads();
    }
}

// ---------------- build: per-(node,rel) counts, offsets, sorted srcs --------
__global__ void zero_build_kernel(int4* __restrict__ cnti,
                                  float* __restrict__ S0, float* __restrict__ S1)
{
    int i = blockIdx.x * blockDim.x + threadIdx.x;
    if (i < NNODE) cnti[i] = make_int4(0, 0, 0, 0);
    if (i < NNODE * 16) { S0[i] = 0.f; S1[i] = 0.f; }
}

__global__ void hist3_kernel(const int* __restrict__ ei0,
                             const int* __restrict__ ei1,
                             const int* __restrict__ ei2,
                             int4* __restrict__ cnti)
{
    int i = blockIdx.x * blockDim.x + threadIdx.x;
    if (i >= NEDGE_TOT) return;
    int r = i / NE, e = i - r * NE;
    const int* ei = (r == 0) ? ei0 : (r == 1) ? ei1 : ei2;
    int dst = ei[NE + e];
    atomicAdd(reinterpret_cast<int*>(cnti + dst) + r, 1);
}

// single-block exclusive scan over per-node totals -> off
__global__ __launch_bounds__(256)
void scan_kernel(const int4* __restrict__ cnti, int* __restrict__ off)
{
    __shared__ int warp_sums[8];
    __shared__ int s_carry;
    const int tid  = threadIdx.x;
    const int lane = tid & 31;
    const int wid  = tid >> 5;
    if (tid == 0) s_carry = 0;
    __syncthreads();

    for (int base = 0; base < NNODE; base += 256) {
        int i = base + tid;
        int x = 0;
        if (i < NNODE) {
            int4 c = cnti[i];
            x = c.x + c.y + c.z;
        }
        int v = x;
#pragma unroll
        for (int d = 1; d < 32; d <<= 1) {
            int t = __shfl_up_sync(0xffffffffu, v, d);
            if (lane >= d) v += t;
        }
        if (lane == 31) warp_sums[wid] = v;
        __syncthreads();
        if (wid == 0 && lane < 8) {
            int s = warp_sums[lane];
#pragma unroll
            for (int d = 1; d < 8; d <<= 1) {
                int t = __shfl_up_sync(0x000000ffu, s, d);
                if (lane >= d) s += t;
            }
            warp_sums[lane] = s;
        }
        __syncthreads();
        int add  = (wid > 0) ? warp_sums[wid - 1] : 0;
        int incl = v + add + s_carry;
        if (i < NNODE) off[i] = incl - x;
        __syncthreads();
        if (tid == 255) s_carry = incl;
        __syncthreads();
    }
    if (tid == 0) off[NNODE] = s_carry;
}

__global__ void cursor3_kernel(const int4* __restrict__ cnti,
                               const int* __restrict__ off,
                               int* __restrict__ cursor3)
{
    int i = blockIdx.x * blockDim.x + threadIdx.x;
    if (i >= NNODE) return;
    int4 c = cnti[i];
    int base = off[i];
    cursor3[i * 3 + 0] = base;
    cursor3[i * 3 + 1] = base + c.x;
    cursor3[i * 3 + 2] = base + c.x + c.y;
}

__global__ void fill3_kernel(const int* __restrict__ ei0,
                             const int* __restrict__ ei1,
                             const int* __restrict__ ei2,
                             int* __restrict__ cursor3,
                             int* __restrict__ srcs)
{
    int i = blockIdx.x * blockDim.x + threadIdx.x;
    if (i >= NEDGE_TOT) return;
    int r = i / NE, e = i - r * NE;
    const int* ei = (r == 0) ? ei0 : (r == 1) ? ei1 : ei2;
    int src = ei[e];
    int dst = ei[NE + e];
    int pos = atomicAdd(cursor3 + dst * 3 + r, 1);
    srcs[pos] = src;
}

// ---------------- edge-attr scatter: S_r[dst] += ea_r[e] --------------------
__global__ void ea_scatter_kernel(const float* __restrict__ ea0,
                                  const float* __restrict__ ea1,
                                  const int* __restrict__ ei0,
                                  const int* __restrict__ ei1,
                                  float* __restrict__ S0, float* __restrict__ S1)
{
    int i = blockIdx.x * blockDim.x + threadIdx.x;
    if (i >= 2 * NE * 16) return;
    int rel = i / (NE * 16);
    int rem = i - rel * (NE * 16);
    int e = rem >> 4;
    int l = rem & 15;
    if (rel == 0) {
        int dst = ei0[NE + e];
        atomicAdd(S0 + (size_t)dst * 16 + l, ea0[(size_t)e * 16 + l]);
    } else {
        int dst = ei1[NE + e];
        atomicAdd(S1 + (size_t)dst * 16 + l, ea1[(size_t)e * 16 + l]);
    }
}

// ---------------- Cterm: per-node, per-layer constant term ------------------
#define CT_NODES 16
__global__ __launch_bounds__(128)
void cterm_kernel(const float* __restrict__ S0, const float* __restrict__ S1,
                  const int4* __restrict__ cnti,
                  const float* __restrict__ node_b, const float* __restrict__ edge_W,
                  const float* __restrict__ edge_b, float* __restrict__ Ct)
{
    const int l   = blockIdx.y;
    const int j   = threadIdx.x;
    __shared__ float eW0[16 * 128];
    __shared__ float eW1[16 * 128];
    __shared__ float nb0[128], nb1[128], nb2[128], eb0[128], eb1[128];
    __shared__ float sS[2][32];

    for (int k = 0; k < 16; k++) {
        eW0[k * 128 + j] = edge_W[((size_t)(l * 2 + 0) * 16 + k) * 128 + j];
        eW1[k * 128 + j] = edge_W[((size_t)(l * 2 + 1) * 16 + k) * 128 + j];
    }
    nb0[j] = node_b[(size_t)(l * 3 + 0) * 128 + j];
    nb1[j] = node_b[(size_t)(l * 3 + 1) * 128 + j];
    nb2[j] = node_b[(size_t)(l * 3 + 2) * 128 + j];
    eb0[j] = edge_b[(size_t)(l * 2 + 0) * 128 + j];
    eb1[j] = edge_b[(size_t)(l * 2 + 1) * 128 + j];
    __syncthreads();

    const int nbase = blockIdx.x * CT_NODES;
    for (int t = 0; t < CT_NODES; t++) {
        int node = nbase + t;
        int buf = t & 1;
        if (j < 16)      sS[buf][j] = S0[(size_t)node * 16 + j];
        else if (j < 32) sS[buf][j] = S1[(size_t)node * 16 + (j - 16)];
        __syncthreads();
        int4 ci = cnti[node];
        float c0 = (float)ci.x;
        float c1 = (float)ci.y;
        float c2 = (float)ci.z;
        float v = c0 * (nb0[j] + eb0[j]) + c1 * (nb1[j] + eb1[j]) + c2 * nb2[j];
#pragma unroll
        for (int k = 0; k < 16; k++) v = fmaf(sS[buf][k], eW0[k * 128 + j], v);
#pragma unroll
        for (int k = 0; k < 16; k++) v = fmaf(sS[buf][k + 16], eW1[k * 128 + j], v);
        Ct[((size_t)l * NNODE + node) * 128 + j] = v;
        __syncthreads();
    }
}

// ---------------- gather: branchless, fp16 H source, warp per (node,bpair) --
#define BPW 2   // batches per warp
__global__ __launch_bounds__(256)
void gather_kernel(const __half2* __restrict__ Hh, const int* __restrict__ off,
                   const int4* __restrict__ cnti, const int* __restrict__ srcs,
                   __half* __restrict__ G)
{
    int gw   = (blockIdx.x * blockDim.x + threadIdx.x) >> 5;
    int lane = threadIdx.x & 31;
    if (gw >= NNODE * 2) return;
    const int node = gw >> 1;
    const int b0   = (gw & 1) * BPW;
    const int jb = off[node];
    const int4 c = cnti[node];
    const int j0e = jb + c.x;
    const int j1e = j0e + c.y;
    const int je  = j1e + c.z;

    float4 a0[BPW], a1[BPW], a2[BPW];
#pragma unroll
    for (int b = 0; b < BPW; b++) {
        a0[b] = make_float4(0.f, 0.f, 0.f, 0.f);
        a1[b] = make_float4(0.f, 0.f, 0.f, 0.f);
        a2[b] = make_float4(0.f, 0.f, 0.f, 0.f);
    }

    const __half2* Hb = Hh + (size_t)(b0 * NNODE) * 64 + lane * 2;

    for (int j = jb; j < j0e; j++) {
        int src = srcs[j];
        const __half2* hb = Hb + (size_t)src * 64;
#pragma unroll
        for (int b = 0; b < BPW; b++) {
            uint2 raw = *reinterpret_cast<const uint2*>(hb + (size_t)b * NNODE * 64);
            float2 f0 = __half22float2(*reinterpret_cast<__half2*>(&raw.x));
            float2 f1 = __half22float2(*reinterpret_cast<__half2*>(&raw.y));
            a0[b].x += f0.x; a0[b].y += f0.y; a0[b].z += f1.x; a0[b].w += f1.y;
        }
    }
    for (int j = j0e; j < j1e; j++) {
        int src = srcs[j];
        const __half2* hb = Hb + (size_t)src * 64;
#pragma unroll
        for (int b = 0; b < BPW; b++) {
            uint2 raw = *reinterpret_cast<const uint2*>(hb + (size_t)b * NNODE * 64);
            float2 f0 = __half22float2(*reinterpret_cast<__half2*>(&raw.x));
            float2 f1 = __half22float2(*reinterpret_cast<__half2*>(&raw.y));
            a1[b].x += f0.x; a1[b].y += f0.y; a1[b].z += f1.x; a1[b].w += f1.y;
        }
    }
    for (int j = j1e; j < je; j++) {
        int src = srcs[j];
        const __half2* hb = Hb + (size_t)src * 64;
#pragma unroll
        for (int b = 0; b < BPW; b++) {
            uint2 raw = *reinterpret_cast<const uint2*>(hb + (size_t)b * NNODE * 64);
            float2 f0 = __half22float2(*reinterpret_cast<__half2*>(&raw.x));
            float2 f1 = __half22float2(*reinterpret_cast<__half2*>(&raw.y));
            a2[b].x += f0.x; a2[b].y += f0.y; a2[b].z += f1.x; a2[b].w += f1.y;
        }
    }

#pragma unroll
    for (int b = 0; b < BPW; b++) {
        __half* gb = G + (size_t)((b0 + b) * NNODE + node) * 384 + lane * 4;
        __half2 p0, p1;
        uint2 v;
        p0 = __floats2half2_rn(a0[b].x, a0[b].y);
        p1 = __floats2half2_rn(a0[b].z, a0[b].w);
        v.x = *reinterpret_cast<uint32_t*>(&p0);
        v.y = *reinterpret_cast<uint32_t*>(&p1);
        *reinterpret_cast<uint2*>(gb) = v;
        p0 = __floats2half2_rn(a1[b].x, a1[b].y);
        p1 = __floats2half2_rn(a1[b].z, a1[b].w);
        v.x = *reinterpret_cast<uint32_t*>(&p0);
        v.y = *reinterpret_cast<uint32_t*>(&p1);
        *reinterpret_cast<uint2*>(gb + 128) = v;
        p0 = __floats2half2_rn(a2[b].x, a2[b].y);
        p1 = __floats2half2_rn(a2[b].z, a2[b].w);
        v.x = *reinterpret_cast<uint32_t*>(&p0);
        v.y = *reinterpret_cast<uint32_t*>(&p1);
        *reinterpret_cast<uint2*>(gb + 256) = v;
    }
}

// ---------------- launch -----------------------------------------------------
extern "C" void kernel_launch(void* const* d_in, const int* in_sizes, int n_in,
                              void* d_out, int out_size)
{
    const float* node_feat = (const float*)d_in[0];
    const float* in_W      = (const float*)d_in[1];
    const float* in_b      = (const float*)d_in[2];
    const float* node_W    = (const float*)d_in[3];
    const float* node_b    = (const float*)d_in[4];
    const float* edge_W    = (const float*)d_in[5];
    const float* edge_b    = (const float*)d_in[6];
    const float* ln_g      = (const float*)d_in[7];
    const float* ln_b      = (const float*)d_in[8];
    const float* ea0       = (const float*)d_in[9];
    const float* ea1       = (const float*)d_in[10];
    const int*   ei0       = (const int*)d_in[11];
    const int*   ei1       = (const int*)d_in[12];
    const int*   ei2       = (const int*)d_in[13];
    float* out = (float*)d_out;

    float *H, *Ct, *S0, *S1;
    __half2* Hh;
    __half* G;
    uint2* Wpre;
    int4* cnti;
    int *off, *cursor3, *srcs;
    cudaGetSymbolAddress((void**)&H,       g_H);
    cudaGetSymbolAddress((void**)&Hh,      g_Hh);
    cudaGetSymbolAddress((void**)&G,       g_G);
    cudaGetSymbolAddress((void**)&Ct,      g_Cterm);
    cudaGetSymbolAddress((void**)&Wpre,    g_Wpre);
    cudaGetSymbolAddress((void**)&S0,      g_S0);
    cudaGetSymbolAddress((void**)&S1,      g_S1);
    cudaGetSymbolAddress((void**)&cnti,    g_cnti);
    cudaGetSymbolAddress((void**)&off,     g_off);
    cudaGetSymbolAddress((void**)&cursor3, g_cursor3);
    cudaGetSymbolAddress((void**)&srcs,    g_srcs);

    // build: counts, offsets, rel-partitioned srcs, edge-attr sums
    zero_build_kernel<<<(NNODE * 16 + 255) / 256, 256>>>(cnti, S0, S1);
    hist3_kernel<<<(NEDGE_TOT + 255) / 256, 256>>>(ei0, ei1, ei2, cnti);
    scan_kernel<<<1, 256>>>(cnti, off);
    cursor3_kernel<<<(NNODE + 255) / 256, 256>>>(cnti, off, cursor3);
    fill3_kernel<<<(NEDGE_TOT + 255) / 256, 256>>>(ei0, ei1, ei2, cursor3, srcs);
    ea_scatter_kernel<<<(2 * NE * 16 + 255) / 256, 256>>>(ea0, ea1, ei0, ei1, S0, S1);
    {
        dim3 grid(NNODE / CT_NODES, NL);
        cterm_kernel<<<grid, 128>>>(S0, S1, cnti, node_b, edge_W, edge_b, Ct);
    }
    prep_w_kernel<<<(NL * 12288 + 255) / 256, 256>>>(node_W, Wpre);

    // input projection (fp32 H + fp16 mirror)
    sgemm128<<<(ROWS + 127) / 128, 256>>>(node_feat, in_W, in_b, H, Hh, ROWS, DN, DM, 0);

    for (int l = 0; l < NL; l++) {
        gather_kernel<<<(NNODE * 2 * 32 + 255) / 256, 256>>>(Hh, off, cnti, srcs, G);
        float* dst = (l == NL - 1) ? out : H;
        gemm_ln_f16<<<ROWS / 128, 256>>>(
            G, Wpre + (size_t)l * 12288, H, Ct + (size_t)l * NNODE * DM,
            ln_g + (size_t)l * DM, ln_b + (size_t)l * DM,
            dst, (l == NL - 1) ? (__half2*)nullptr : Hh);
    }
}